// round 13
// baseline (speedup 1.0000x reference)
#include <cuda_runtime.h>
#include <cuda_fp16.h>
#include <cstdint>

#define T_   10
#define N_   50000
#define R_   50000
#define DIN_ 128
#define D_   64
#define H_   4
#define E_   400000
#define MTOT (T_ * N_)   // 500000
#define SCAN_BLK 4096
#define NSCAN ((MTOT + SCAN_BLK - 1) / SCAN_BLK)   // 123

// ---------------- scratch ----------------
__device__ float2 g_degcnt[(size_t)MTOT];
__device__ float  g_deg[(size_t)MTOT];
__device__ int    g_offs[(size_t)MTOT];
__device__ int    g_offw[(size_t)MTOT];
__device__ int    g_bsum[256];
__device__ int2   g_bucket[(size_t)T_ * E_];
__device__ __half g_hwh[(size_t)MTOT * D_];
__device__ __half g_h1 [(size_t)MTOT * D_];
__device__ __half g_h2 [(size_t)MTOT * D_];
__device__ __half g_k  [(size_t)R_ * T_ * D_];
__device__ __half g_v  [(size_t)R_ * T_ * D_];
__device__ float  g_te9[(size_t)R_ * D_];

// ---------------- init / degree+count (fused vector RED) ----------------
__global__ void init_k(float2* degcnt) {
    int i = blockIdx.x * blockDim.x + threadIdx.x;
    if (i < MTOT) degcnt[i] = make_float2(1.0f, 0.0f);
}
__global__ void pass1_k(float2* degcnt, const int* __restrict__ edge_index,
                        const float* __restrict__ ew) {
    int t = blockIdx.y;
    int e = blockIdx.x * blockDim.x + threadIdx.x;
    if (e < E_) {
        int d = __ldg(edge_index + (size_t)t * 2 * E_ + E_ + e);
        float w = __ldg(ew + (size_t)t * E_ + e);
        float* p = (float*)&degcnt[t * N_ + d];
        asm volatile("red.global.add.v2.f32 [%0], {%1,%2};"
                     :: "l"(p), "f"(w), "f"(1.0f) : "memory");
    }
}

// ---------------- scan ----------------
__global__ void scan1_k(const float2* __restrict__ degcnt, int* __restrict__ offs,
                        int* __restrict__ bsum) {
    __shared__ int ts[256];
    int b = blockIdx.x, tid = threadIdx.x;
    int base = b * SCAN_BLK + tid * 16;
    int v[16]; int s = 0;
#pragma unroll
    for (int i = 0; i < 16; i++) {
        int idx = base + i;
        v[i] = (idx < MTOT) ? (int)__ldg(&degcnt[idx].y) : 0;
        s += v[i];
    }
    ts[tid] = s;
    __syncthreads();
    for (int off = 1; off < 256; off <<= 1) {
        int x = (tid >= off) ? ts[tid - off] : 0;
        __syncthreads();
        ts[tid] += x;
        __syncthreads();
    }
    int excl = ts[tid] - s;
    if (tid == 255) bsum[b] = ts[255];
    int run = excl;
#pragma unroll
    for (int i = 0; i < 16; i++) {
        int idx = base + i;
        if (idx < MTOT) offs[idx] = run;
        run += v[i];
    }
}
__global__ void scan2_k(int* bsum, int nb) {
    __shared__ int s[128];
    int tid = threadIdx.x;
    int v = (tid < nb) ? bsum[tid] : 0;
    s[tid] = v;
    __syncthreads();
    for (int off = 1; off < 128; off <<= 1) {
        int x = (tid >= off) ? s[tid - off] : 0;
        __syncthreads();
        s[tid] += x;
        __syncthreads();
    }
    if (tid < nb) bsum[tid] = s[tid] - v;
}
__global__ void scan3_k(int* __restrict__ offs, int* __restrict__ offw,
                        const int* __restrict__ bsum, const float2* __restrict__ degcnt,
                        float* __restrict__ dinv) {
    int i = blockIdx.x * blockDim.x + threadIdx.x;
    if (i < MTOT) {
        int v = offs[i] + bsum[i >> 12];
        offs[i] = v;
        offw[i] = v;
        dinv[i] = rsqrtf(__ldg(&degcnt[i].x));
    }
}

// ---------------- scatter edges into CSR buckets ----------------
__global__ void scatter_k(const int* __restrict__ edge_index, const float* __restrict__ ew,
                          const float* __restrict__ dinv, int* __restrict__ offw,
                          int2* __restrict__ bucket) {
    int t = blockIdx.y;
    int e = blockIdx.x * blockDim.x + threadIdx.x;
    if (e >= E_) return;
    const int* src = edge_index + (size_t)t * 2 * E_;
    int s = __ldg(src + e), d = __ldg(src + E_ + e);
    float w = __ldg(ew + (size_t)t * E_ + e);
    float c = __ldg(dinv + t * N_ + s) * w * __ldg(dinv + t * N_ + d);
    int pos = atomicAdd(&offw[t * N_ + d], 1);
    bucket[pos] = make_int2(s, __float_as_int(c));
}

// ---------------- gather aggregation (fp16 src, fp32 acc, fp16 out, 4x edge ILP) ----------------
__device__ __forceinline__ void acc_half8(float4& a0, float4& a1, float c, uint4 raw) {
    const __half2* h = (const __half2*)&raw;
    float2 f0 = __half22float2(h[0]);
    float2 f1 = __half22float2(h[1]);
    float2 f2 = __half22float2(h[2]);
    float2 f3 = __half22float2(h[3]);
    a0.x = fmaf(c, f0.x, a0.x); a0.y = fmaf(c, f0.y, a0.y);
    a0.z = fmaf(c, f1.x, a0.z); a0.w = fmaf(c, f1.y, a0.w);
    a1.x = fmaf(c, f2.x, a1.x); a1.y = fmaf(c, f2.y, a1.y);
    a1.z = fmaf(c, f3.x, a1.z); a1.w = fmaf(c, f3.y, a1.w);
}

__global__ void agg2_k(const int2* __restrict__ bucket, const int* __restrict__ offs,
                       const int* __restrict__ offw, const float* __restrict__ dinv,
                       const __half* __restrict__ hwh, __half* __restrict__ out) {
    int idx = blockIdx.x * blockDim.x + threadIdx.x;
    int node = idx >> 3, sub = idx & 7;
    if (node >= MTOT) return;
    long long tb = (long long)(node / N_) * N_;
    float di = __ldg(dinv + node);
    float s2 = di * di;
    float4 acc0 = make_float4(0.f, 0.f, 0.f, 0.f);
    float4 acc1 = make_float4(0.f, 0.f, 0.f, 0.f);
    uint4 sv = __ldg((const uint4*)(hwh + (size_t)node * 64) + sub);
    acc_half8(acc0, acc1, s2, sv);
    int p = __ldg(offs + node), e = __ldg(offw + node);
    for (; p + 4 <= e; p += 4) {
        int2 e0 = __ldg(bucket + p);
        int2 e1 = __ldg(bucket + p + 1);
        int2 e2 = __ldg(bucket + p + 2);
        int2 e3 = __ldg(bucket + p + 3);
        uint4 g0 = __ldg((const uint4*)(hwh + (size_t)(tb + e0.x) * 64) + sub);
        uint4 g1 = __ldg((const uint4*)(hwh + (size_t)(tb + e1.x) * 64) + sub);
        uint4 g2 = __ldg((const uint4*)(hwh + (size_t)(tb + e2.x) * 64) + sub);
        uint4 g3 = __ldg((const uint4*)(hwh + (size_t)(tb + e3.x) * 64) + sub);
        acc_half8(acc0, acc1, __int_as_float(e0.y), g0);
        acc_half8(acc0, acc1, __int_as_float(e1.y), g1);
        acc_half8(acc0, acc1, __int_as_float(e2.y), g2);
        acc_half8(acc0, acc1, __int_as_float(e3.y), g3);
    }
    for (; p + 2 <= e; p += 2) {
        int2 e0 = __ldg(bucket + p);
        int2 e1 = __ldg(bucket + p + 1);
        uint4 g0 = __ldg((const uint4*)(hwh + (size_t)(tb + e0.x) * 64) + sub);
        uint4 g1 = __ldg((const uint4*)(hwh + (size_t)(tb + e1.x) * 64) + sub);
        acc_half8(acc0, acc1, __int_as_float(e0.y), g0);
        acc_half8(acc0, acc1, __int_as_float(e1.y), g1);
    }
    if (p < e) {
        int2 ed = __ldg(bucket + p);
        uint4 gv = __ldg((const uint4*)(hwh + (size_t)(tb + ed.x) * 64) + sub);
        acc_half8(acc0, acc1, __int_as_float(ed.y), gv);
    }
    __half2 h0 = __floats2half2_rn(acc0.x, acc0.y);
    __half2 h1 = __floats2half2_rn(acc0.z, acc0.w);
    __half2 h2 = __floats2half2_rn(acc1.x, acc1.y);
    __half2 h3 = __floats2half2_rn(acc1.z, acc1.w);
    uint4 pk;
    pk.x = *(unsigned*)&h0; pk.y = *(unsigned*)&h1;
    pk.z = *(unsigned*)&h2; pk.w = *(unsigned*)&h3;
    ((uint4*)(out + (size_t)node * 64))[sub] = pk;
}

// ---------------- tf32 helpers ----------------
__device__ __forceinline__ void mma_tf32(float* c, unsigned a0, unsigned a1,
                                         unsigned a2, unsigned a3,
                                         unsigned b0, unsigned b1) {
    asm volatile(
        "mma.sync.aligned.m16n8k8.row.col.f32.tf32.tf32.f32 "
        "{%0,%1,%2,%3}, {%4,%5,%6,%7}, {%8,%9}, {%0,%1,%2,%3};"
        : "+f"(c[0]), "+f"(c[1]), "+f"(c[2]), "+f"(c[3])
        : "r"(a0), "r"(a1), "r"(a2), "r"(a3), "r"(b0), "r"(b1));
}
__device__ __forceinline__ void split_tf32(float f, unsigned& hi, unsigned& lo) {
    unsigned u = __float_as_uint(f) & 0xFFFFE000u;
    hi = u;
    lo = __float_as_uint(f - __uint_as_float(u));
}

__device__ __forceinline__ float4 load_h4_relu(const __half* p, const float* bias, int boff) {
    __half2 a = __ldg((const __half2*)p);
    __half2 b = __ldg((const __half2*)p + 1);
    float2 lo = __half22float2(a), hi = __half22float2(b);
    float4 bb = *(const float4*)(bias + boff);
    float4 v;
    v.x = fmaxf(lo.x + bb.x, 0.f);
    v.y = fmaxf(lo.y + bb.y, 0.f);
    v.z = fmaxf(hi.x + bb.z, 0.f);
    v.w = fmaxf(hi.y + bb.w, 0.f);
    return v;
}

// ---------------- layer-1 GEMM: cp.async 4-stage, fp32 in, fp16 out ----------------
__global__ void __launch_bounds__(256, 2)
gemm1_ca_k(const float* __restrict__ A, const float* __restrict__ Wsrc,
           __half* __restrict__ hwh) {
    constexpr int K = 128, BM = 128, BK = 32, NT = 4;
    constexpr int WPAD = K + 4;
    constexpr int APAD = BK + 4;

    extern __shared__ float sm[];
    float* Wsh = sm;
    float* Ash = sm + 64 * WPAD;

    const int tid = threadIdx.x;
    const int wid = tid >> 5, lane = tid & 31;
    const int warp_m = wid & 3, warp_n = wid >> 2;
    const int lg = lane >> 2, lt = lane & 3;
    const long long row0 = (long long)blockIdx.x * BM;

#pragma unroll
    for (int kt = 0; kt < NT; kt++) {
        float* dstbase = Ash + kt * BM * APAD;
#pragma unroll
        for (int it = 0; it < 4; it++) {
            int idx = it * 256 + tid;
            int r = idx >> 3, kq = idx & 7;
            long long grow = row0 + r;
            long long srow = (grow < MTOT) ? grow : 0;
            const float* src = A + srow * K + kt * BK + kq * 4;
            unsigned dst = (unsigned)__cvta_generic_to_shared(dstbase + r * APAD + kq * 4);
            int nbytes = (grow < MTOT) ? 16 : 0;
            asm volatile("cp.async.cg.shared.global [%0], [%1], 16, %2;"
                         :: "r"(dst), "l"(src), "r"(nbytes) : "memory");
        }
        asm volatile("cp.async.commit_group;" ::: "memory");
    }

    for (int i = tid * 4; i < 64 * K; i += 256 * 4) {
        int n = i / K, k = i % K;
        float4 w = *(const float4*)(Wsrc + n * K + k);
        *(float4*)(Wsh + n * WPAD + k) = w;
    }

    float c[2][4][4];
#pragma unroll
    for (int mt = 0; mt < 2; mt++)
#pragma unroll
        for (int nt = 0; nt < 4; nt++)
#pragma unroll
            for (int i = 0; i < 4; i++) c[mt][nt][i] = 0.f;

#pragma unroll
    for (int kt = 0; kt < NT; kt++) {
        if (kt == 0)      asm volatile("cp.async.wait_group 3;" ::: "memory");
        else if (kt == 1) asm volatile("cp.async.wait_group 2;" ::: "memory");
        else if (kt == 2) asm volatile("cp.async.wait_group 1;" ::: "memory");
        else              asm volatile("cp.async.wait_group 0;" ::: "memory");
        __syncthreads();
        const float* As = Ash + kt * BM * APAD;
#pragma unroll
        for (int ks = 0; ks < 4; ks++) {
            const int k0 = ks * 8 + lt;
            unsigned ahi[2][4], alo[2][4];
#pragma unroll
            for (int mt = 0; mt < 2; mt++) {
                int ar = warp_m * 32 + mt * 16 + lg;
                float f0 = As[ar * APAD + k0];
                float f1 = As[(ar + 8) * APAD + k0];
                float f2 = As[ar * APAD + k0 + 4];
                float f3 = As[(ar + 8) * APAD + k0 + 4];
                split_tf32(f0, ahi[mt][0], alo[mt][0]);
                split_tf32(f1, ahi[mt][1], alo[mt][1]);
                split_tf32(f2, ahi[mt][2], alo[mt][2]);
                split_tf32(f3, ahi[mt][3], alo[mt][3]);
            }
            unsigned bhi[4][2], blo[4][2];
#pragma unroll
            for (int nt = 0; nt < 4; nt++) {
                int bn = warp_n * 32 + nt * 8 + lg;
                float g0 = Wsh[bn * WPAD + kt * BK + k0];
                float g1 = Wsh[bn * WPAD + kt * BK + k0 + 4];
                split_tf32(g0, bhi[nt][0], blo[nt][0]);
                split_tf32(g1, bhi[nt][1], blo[nt][1]);
            }
#pragma unroll
            for (int mt = 0; mt < 2; mt++)
#pragma unroll
                for (int nt = 0; nt < 4; nt++) {
                    mma_tf32(c[mt][nt], ahi[mt][0], ahi[mt][1], ahi[mt][2], ahi[mt][3],
                             bhi[nt][0], bhi[nt][1]);
                    mma_tf32(c[mt][nt], alo[mt][0], alo[mt][1], alo[mt][2], alo[mt][3],
                             bhi[nt][0], bhi[nt][1]);
                    mma_tf32(c[mt][nt], ahi[mt][0], ahi[mt][1], ahi[mt][2], ahi[mt][3],
                             blo[nt][0], blo[nt][1]);
                }
        }
    }

#pragma unroll
    for (int mt = 0; mt < 2; mt++) {
        long long r_lo = row0 + warp_m * 32 + mt * 16 + lg;
#pragma unroll
        for (int half = 0; half < 2; half++) {
            long long r = r_lo + half * 8;
            if (r >= MTOT) continue;
#pragma unroll
            for (int nt = 0; nt < 4; nt++) {
                int col = warp_n * 32 + nt * 8 + 2 * lt;
                *(__half2*)(hwh + r * 64 + col) =
                    __floats2half2_rn(c[mt][nt][half * 2 + 0], c[mt][nt][half * 2 + 1]);
            }
        }
    }
}

// ---------------- layer-2 GEMM (K=64, fp16 A with relu(A+b) on load, fp16 out) ----------------
__global__ void __launch_bounds__(256, 2)
gemm2_k(const __half* __restrict__ A, const float* __restrict__ Wsrc,
        const float* __restrict__ abias, __half* __restrict__ hwh) {
    constexpr int K = 64, BM = 128, BK = 32, NT = 2;
    constexpr int WPAD = K + 4;
    constexpr int APAD = BK + 4;

    extern __shared__ float sm[];
    float* Wsh = sm;
    float* Ash = sm + 64 * WPAD;

    const int tid = threadIdx.x;
    const int wid = tid >> 5, lane = tid & 31;
    const int warp_m = wid & 3, warp_n = wid >> 2;
    const int lg = lane >> 2, lt = lane & 3;
    const long long row0 = (long long)blockIdx.x * BM;

    for (int i = tid * 4; i < 64 * K; i += 256 * 4) {
        int n = i / K, k = i % K;
        float4 w = *(const float4*)(Wsrc + n * K + k);
        *(float4*)(Wsh + n * WPAD + k) = w;
    }

    float4 areg[4];
    auto lda = [&](int kt) {
#pragma unroll
        for (int it = 0; it < 4; it++) {
            int idx = it * 256 + tid;
            int r = idx >> 3, kq = idx & 7;
            long long grow = row0 + r;
            float4 v = make_float4(0.f, 0.f, 0.f, 0.f);
            if (grow < MTOT)
                v = load_h4_relu(A + grow * K + kt * BK + kq * 4, abias, kt * BK + kq * 4);
            areg[it] = v;
        }
    };
    auto sts = [&](int buf) {
        float* dst = Ash + buf * BM * APAD;
#pragma unroll
        for (int it = 0; it < 4; it++) {
            int idx = it * 256 + tid;
            int r = idx >> 3, kq = idx & 7;
            *(float4*)(dst + r * APAD + kq * 4) = areg[it];
        }
    };

    float c[2][4][4];
#pragma unroll
    for (int mt = 0; mt < 2; mt++)
#pragma unroll
        for (int nt = 0; nt < 4; nt++)
#pragma unroll
            for (int i = 0; i < 4; i++) c[mt][nt][i] = 0.f;

    lda(0);
    sts(0);

    for (int kt = 0; kt < NT; kt++) {
        __syncthreads();
        if (kt + 1 < NT) lda(kt + 1);
        const float* As = Ash + (kt & 1) * BM * APAD;
#pragma unroll
        for (int ks = 0; ks < 4; ks++) {
            const int k0 = ks * 8 + lt;
            unsigned ahi[2][4], alo[2][4];
#pragma unroll
            for (int mt = 0; mt < 2; mt++) {
                int ar = warp_m * 32 + mt * 16 + lg;
                float f0 = As[ar * APAD + k0];
                float f1 = As[(ar + 8) * APAD + k0];
                float f2 = As[ar * APAD + k0 + 4];
                float f3 = As[(ar + 8) * APAD + k0 + 4];
                split_tf32(f0, ahi[mt][0], alo[mt][0]);
                split_tf32(f1, ahi[mt][1], alo[mt][1]);
                split_tf32(f2, ahi[mt][2], alo[mt][2]);
                split_tf32(f3, ahi[mt][3], alo[mt][3]);
            }
            unsigned bhi[4][2], blo[4][2];
#pragma unroll
            for (int nt = 0; nt < 4; nt++) {
                int bn = warp_n * 32 + nt * 8 + lg;
                float g0 = Wsh[bn * WPAD + kt * BK + k0];
                float g1 = Wsh[bn * WPAD + kt * BK + k0 + 4];
                split_tf32(g0, bhi[nt][0], blo[nt][0]);
                split_tf32(g1, bhi[nt][1], blo[nt][1]);
            }
#pragma unroll
            for (int mt = 0; mt < 2; mt++)
#pragma unroll
                for (int nt = 0; nt < 4; nt++) {
                    mma_tf32(c[mt][nt], ahi[mt][0], ahi[mt][1], ahi[mt][2], ahi[mt][3],
                             bhi[nt][0], bhi[nt][1]);
                    mma_tf32(c[mt][nt], alo[mt][0], alo[mt][1], alo[mt][2], alo[mt][3],
                             bhi[nt][0], bhi[nt][1]);
                    mma_tf32(c[mt][nt], ahi[mt][0], ahi[mt][1], ahi[mt][2], ahi[mt][3],
                             blo[nt][0], blo[nt][1]);
                }
        }
        if (kt + 1 < NT) sts((kt + 1) & 1);
    }

#pragma unroll
    for (int mt = 0; mt < 2; mt++) {
        long long r_lo = row0 + warp_m * 32 + mt * 16 + lg;
#pragma unroll
        for (int half = 0; half < 2; half++) {
            long long r = r_lo + half * 8;
            if (r >= MTOT) continue;
#pragma unroll
            for (int nt = 0; nt < 4; nt++) {
                int col = warp_n * 32 + nt * 8 + 2 * lt;
                *(__half2*)(hwh + r * 64 + col) =
                    __floats2half2_rn(c[mt][nt][half * 2 + 0], c[mt][nt][half * 2 + 1]);
            }
        }
    }
}

// ---------------- merged K+V projection GEMM (fp16 A in, fp16 scatter out, te9 fused) ----------------
__global__ void __launch_bounds__(512, 1)
gemm_kv_k(const __half* __restrict__ A, const float* __restrict__ Wsrc,
          const float* __restrict__ abias, const float* __restrict__ ebias,
          const int* __restrict__ gidx, __half* __restrict__ gK, __half* __restrict__ gV,
          float* __restrict__ te9) {
    constexpr int K = 64, BM = 128, BK = 32, NT = 2;
    constexpr int WPAD = K + 4;
    constexpr int APAD = BK + 4;

    extern __shared__ float sm[];
    float* Wsh = sm;
    float* Ash = sm + 128 * WPAD;

    const int tid = threadIdx.x;
    const int wid = tid >> 5, lane = tid & 31;
    const int warp_m = wid & 3, warp_n = wid >> 2;
    const int lg = lane >> 2, lt = lane & 3;
    const long long row0 = (long long)blockIdx.x * BM;

    for (int i = tid * 4; i < 128 * K; i += 512 * 4) {
        int n = i / K, k = i % K;
        float4 w = *(const float4*)(Wsrc + n * K + k);
        *(float4*)(Wsh + n * WPAD + k) = w;
    }

    float4 areg[2];
    auto lda = [&](int kt) {
#pragma unroll
        for (int it = 0; it < 2; it++) {
            int idx = it * 512 + tid;
            int r = idx >> 3, kq = idx & 7;
            long long grow = row0 + r;
            float4 v = make_float4(0.f, 0.f, 0.f, 0.f);
            if (grow < MTOT) {
                v = load_h4_relu(A + grow * K + kt * BK + kq * 4, abias, kt * BK + kq * 4);
                if (grow >= (long long)9 * N_) {   // te9 fusion (t == 9)
                    int n = (int)(grow - (long long)9 * N_);
                    int ridx = __ldg(gidx + (size_t)9 * R_ + n);
                    *(float4*)(te9 + (size_t)ridx * 64 + kt * BK + kq * 4) = v;
                }
            }
            areg[it] = v;
        }
    };
    auto sts = [&](int buf) {
        float* dst = Ash + buf * BM * APAD;
#pragma unroll
        for (int it = 0; it < 2; it++) {
            int idx = it * 512 + tid;
            int r = idx >> 3, kq = idx & 7;
            *(float4*)(dst + r * APAD + kq * 4) = areg[it];
        }
    };

    float c[2][4][4];
#pragma unroll
    for (int mt = 0; mt < 2; mt++)
#pragma unroll
        for (int nt = 0; nt < 4; nt++)
#pragma unroll
            for (int i = 0; i < 4; i++) c[mt][nt][i] = 0.f;

    lda(0);
    sts(0);

    for (int kt = 0; kt < NT; kt++) {
        __syncthreads();
        if (kt + 1 < NT) lda(kt + 1);
        const float* As = Ash + (kt & 1) * BM * APAD;
#pragma unroll
        for (int ks = 0; ks < 4; ks++) {
            const int k0 = ks * 8 + lt;
            unsigned ahi[2][4], alo[2][4];
#pragma unroll
            for (int mt = 0; mt < 2; mt++) {
                int ar = warp_m * 32 + mt * 16 + lg;
                float f0 = As[ar * APAD + k0];
                float f1 = As[(ar + 8) * APAD + k0];
                float f2 = As[ar * APAD + k0 + 4];
                float f3 = As[(ar + 8) * APAD + k0 + 4];
                split_tf32(f0, ahi[mt][0], alo[mt][0]);
                split_tf32(f1, ahi[mt][1], alo[mt][1]);
                split_tf32(f2, ahi[mt][2], alo[mt][2]);
                split_tf32(f3, ahi[mt][3], alo[mt][3]);
            }
            unsigned bhi[4][2], blo[4][2];
#pragma unroll
            for (int nt = 0; nt < 4; nt++) {
                int bn = warp_n * 32 + nt * 8 + lg;
                float g0 = Wsh[bn * WPAD + kt * BK + k0];
                float g1 = Wsh[bn * WPAD + kt * BK + k0 + 4];
                split_tf32(g0, bhi[nt][0], blo[nt][0]);
                split_tf32(g1, bhi[nt][1], blo[nt][1]);
            }
#pragma unroll
            for (int mt = 0; mt < 2; mt++)
#pragma unroll
                for (int nt = 0; nt < 4; nt++) {
                    mma_tf32(c[mt][nt], ahi[mt][0], ahi[mt][1], ahi[mt][2], ahi[mt][3],
                             bhi[nt][0], bhi[nt][1]);
                    mma_tf32(c[mt][nt], alo[mt][0], alo[mt][1], alo[mt][2], alo[mt][3],
                             bhi[nt][0], bhi[nt][1]);
                    mma_tf32(c[mt][nt], ahi[mt][0], ahi[mt][1], ahi[mt][2], ahi[mt][3],
                             blo[nt][0], blo[nt][1]);
                }
        }
        if (kt + 1 < NT) sts((kt + 1) & 1);
    }

#pragma unroll
    for (int mt = 0; mt < 2; mt++) {
        long long r_lo = row0 + warp_m * 32 + mt * 16 + lg;
#pragma unroll
        for (int half = 0; half < 2; half++) {
            long long r = r_lo + half * 8;
            if (r >= MTOT) continue;
            unsigned rr = (unsigned)r;
            unsigned t = rr / (unsigned)N_;
            unsigned n = rr - t * (unsigned)N_;
            int ridx = __ldg(gidx + (size_t)t * R_ + n);
            size_t rowoff = ((size_t)ridx * T_ + t) * 64;
#pragma unroll
            for (int nt = 0; nt < 4; nt++) {
                int col = warp_n * 32 + nt * 8 + 2 * lt;
                float2 b = *(const float2*)(ebias + col);
                __half* base = (col < 64 ? gK + rowoff + col : gV + rowoff + (col - 64));
                *(__half2*)base = __floats2half2_rn(c[mt][nt][half * 2 + 0] + b.x,
                                                    c[mt][nt][half * 2 + 1] + b.y);
            }
        }
    }
}

// ---------------- tail ----------------
#define TAIL_WARPS 8
#define TAIL_SMEM  ((12288 + 704 + TAIL_WARPS * 1456) * 4)

__device__ __forceinline__ float warp_sum(float v) {
#pragma unroll
    for (int off = 16; off; off >>= 1) v += __shfl_xor_sync(0xffffffffu, v, off);
    return v;
}

__global__ void tail_k(const float* __restrict__ inW, const float* __restrict__ inB,
                       const float* __restrict__ outW, const float* __restrict__ outB,
                       const float* __restrict__ w1, const float* __restrict__ w2,
                       const float* __restrict__ w3, const float* __restrict__ w4,
                       const float* __restrict__ ln1g, const float* __restrict__ ln1b,
                       const float* __restrict__ ln2g, const float* __restrict__ ln2b,
                       const float* __restrict__ fcW, const float* __restrict__ fcB,
                       const float* __restrict__ te9, const __half* __restrict__ gK,
                       const __half* __restrict__ gV, float* __restrict__ out) {
    extern __shared__ float sh[];
    float* Wq = sh;
    float* Wo = sh + 4096;
    float* Wf = sh + 8192;
    float* cv = sh + 12288;

    int tid = threadIdx.x;
    for (int i = tid; i < 4096; i += TAIL_WARPS * 32) {
        int k = i >> 6, j = i & 63;
        Wq[i] = inW[j * 64 + k];
        Wo[i] = outW[j * 64 + k];
        Wf[i] = fcW[j * 64 + k];
    }
    if (tid < 64) {
        cv[tid]       = inB[tid];
        cv[64 + tid]  = outB[tid];
        cv[128 + tid] = fcB[tid];
        cv[192 + tid] = w1[(T_ - 1) * 64 + tid];
        cv[256 + tid] = w2[(T_ - 1) * 64 + tid];
        cv[320 + tid] = ln1g[tid];
        cv[384 + tid] = ln1b[tid];
        cv[448 + tid] = w3[tid];
        cv[512 + tid] = w4[tid];
        cv[576 + tid] = ln2g[tid];
        cv[640 + tid] = ln2b[tid];
    }
    __syncthreads();

    int warp = tid >> 5, lane = tid & 31;
    float* wb   = cv + 704 + warp * 1456;
    float* pvec = wb;
    float* pq   = wb + 64;
    float* kb   = wb + 128;
    float* vb   = wb + 768;
    float* sc   = wb + 1408;

    int gw = blockIdx.x * TAIL_WARPS + warp;
    int nw = gridDim.x * TAIL_WARPS;

    for (int r = gw; r < R_; r += nw) {
        pvec[lane]      = te9[(size_t)r * 64 + lane];
        pvec[lane + 32] = te9[(size_t)r * 64 + lane + 32];
        const __half2* kr = (const __half2*)(gK + (size_t)r * 640);
        const __half2* vr = (const __half2*)(gV + (size_t)r * 640);
        for (int i = lane; i < 320; i += 32) {
            *(float2*)(kb + 2 * i) = __half22float2(__ldg(kr + i));
            *(float2*)(vb + 2 * i) = __half22float2(__ldg(vr + i));
        }
        __syncwarp();

        float q0 = cv[lane], q1 = cv[lane + 32];
        for (int k = 0; k < 64; k++) {
            float xv = pvec[k];
            q0 = fmaf(xv, Wq[k * 64 + lane], q0);
            q1 = fmaf(xv, Wq[k * 64 + lane + 32], q1);
        }
        pq[lane] = q0; pq[lane + 32] = q1;
        __syncwarp();

        for (int p = lane; p < H_ * T_; p += 32) {
            int h = p / T_, tt = p - h * T_;
            const float* qh = pq + h * 16;
            const float* kh = kb + tt * 64 + h * 16;
            float s = 0.f;
#pragma unroll
            for (int d = 0; d < 16; d++) s = fmaf(qh[d], kh[d], s);
            sc[p] = s * 0.25f;
        }
        __syncwarp();

        if (lane < H_) {
            float mx = -1e30f;
#pragma unroll
            for (int tt = 0; tt < T_; tt++) mx = fmaxf(mx, sc[lane * T_ + tt]);
            float sm = 0.f;
#pragma unroll
            for (int tt = 0; tt < T_; tt++) {
                float ev = __expf(sc[lane * T_ + tt] - mx);
                sc[lane * T_ + tt] = ev; sm += ev;
            }
            float inv = 1.f / sm;
#pragma unroll
            for (int tt = 0; tt < T_; tt++) sc[lane * T_ + tt] *= inv;
        }
        __syncwarp();

        int h0 = lane >> 4, h1 = (lane + 32) >> 4;
        float a0 = 0.f, a1 = 0.f;
#pragma unroll
        for (int tt = 0; tt < T_; tt++) {
            a0 = fmaf(sc[h0 * T_ + tt], vb[tt * 64 + lane], a0);
            a1 = fmaf(sc[h1 * T_ + tt], vb[tt * 64 + lane + 32], a1);
        }
        pq[lane] = a0; pq[lane + 32] = a1;
        __syncwarp();

        float o0 = cv[64 + lane], o1 = cv[64 + lane + 32];
        for (int k = 0; k < 64; k++) {
            float xv = pq[k];
            o0 = fmaf(xv, Wo[k * 64 + lane], o0);
            o1 = fmaf(xv, Wo[k * 64 + lane + 32], o1);
        }

        float y0 = cv[192 + lane] * pvec[lane] + cv[256 + lane] * o0;
        float y1 = cv[192 + lane + 32] * pvec[lane + 32] + cv[256 + lane + 32] * o1;
        float mu = warp_sum(y0 + y1) * (1.f / 64.f);
        float d0 = y0 - mu, d1 = y1 - mu;
        float var = warp_sum(d0 * d0 + d1 * d1) * (1.f / 64.f);
        float rs = rsqrtf(var + 1e-5f);
        float f0 = d0 * rs * cv[320 + lane] + cv[384 + lane];
        float f1 = d1 * rs * cv[320 + lane + 32] + cv[384 + lane + 32];
        __syncwarp();
        pvec[lane] = f0; pvec[lane + 32] = f1;
        __syncwarp();

        float u0 = cv[128 + lane], u1 = cv[128 + lane + 32];
        for (int k = 0; k < 64; k++) {
            float xv = pvec[k];
            u0 = fmaf(xv, Wf[k * 64 + lane], u0);
            u1 = fmaf(xv, Wf[k * 64 + lane + 32], u1);
        }
        float z0 = cv[448 + lane] * f0 + cv[512 + lane] * u0;
        float z1 = cv[448 + lane + 32] * f1 + cv[512 + lane + 32] * u1;
        float mu2 = warp_sum(z0 + z1) * (1.f / 64.f);
        float e0 = z0 - mu2, e1 = z1 - mu2;
        float var2 = warp_sum(e0 * e0 + e1 * e1) * (1.f / 64.f);
        float rs2 = rsqrtf(var2 + 1e-5f);
        out[(size_t)r * 64 + lane]      = e0 * rs2 * cv[576 + lane] + cv[640 + lane];
        out[(size_t)r * 64 + lane + 32] = e1 * rs2 * cv[576 + lane + 32] + cv[640 + lane + 32];
        __syncwarp();
    }
}

// ---------------- launch ----------------
extern "C" void kernel_launch(void* const* d_in, const int* in_sizes, int n_in,
                              void* d_out, int out_size) {
    const float* x          = (const float*)d_in[0];
    const int*   edge_index = (const int*)  d_in[1];
    const float* edge_weight= (const float*)d_in[2];
    const int*   global_idx = (const int*)  d_in[3];
    const float* gcn1_w     = (const float*)d_in[4];
    const float* gcn1_b     = (const float*)d_in[5];
    const float* gcn2_w     = (const float*)d_in[6];
    const float* gcn2_b     = (const float*)d_in[7];
    const float* in_proj_w  = (const float*)d_in[8];
    const float* in_proj_b  = (const float*)d_in[9];
    const float* out_proj_w = (const float*)d_in[10];
    const float* out_proj_b = (const float*)d_in[11];
    const float* w1         = (const float*)d_in[12];
    const float* w2         = (const float*)d_in[13];
    const float* w3         = (const float*)d_in[14];
    const float* w4         = (const float*)d_in[15];
    const float* ln1_g      = (const float*)d_in[16];
    const float* ln1_b      = (const float*)d_in[17];
    const float* ln2_g      = (const float*)d_in[18];
    const float* ln2_b      = (const float*)d_in[19];
    const float* fc_w       = (const float*)d_in[20];
    const float* fc_b       = (const float*)d_in[21];
    float* out = (float*)d_out;

    float *deg, *te9;
    float2* degcnt;
    __half *hwh, *h1, *h2, *gk, *gv;
    int *offs, *offw, *bsum;
    int2* bucket;
    cudaGetSymbolAddress((void**)&degcnt, g_degcnt);
    cudaGetSymbolAddress((void**)&deg,  g_deg);
    cudaGetSymbolAddress((void**)&offs, g_offs);
    cudaGetSymbolAddress((void**)&offw, g_offw);
    cudaGetSymbolAddress((void**)&bsum, g_bsum);
    cudaGetSymbolAddress((void**)&bucket, g_bucket);
    cudaGetSymbolAddress((void**)&hwh, g_hwh);
    cudaGetSymbolAddress((void**)&h1,  g_h1);
    cudaGetSymbolAddress((void**)&h2,  g_h2);
    cudaGetSymbolAddress((void**)&gk,  g_k);
    cudaGetSymbolAddress((void**)&gv,  g_v);
    cudaGetSymbolAddress((void**)&te9, g_te9);

    const int SM_G1 = (64 * (128 + 4) + 4 * 128 * 36) * 4;   // 107520
    const int SM_G2 = (64 * (64 + 4)  + 2 * 128 * 36) * 4;   // 54272
    const int SM_KV = (128 * (64 + 4) + 2 * 128 * 36) * 4;   // 71680
    cudaFuncSetAttribute((const void*)gemm1_ca_k,
                         cudaFuncAttributeMaxDynamicSharedMemorySize, SM_G1);
    cudaFuncSetAttribute((const void*)gemm2_k,
                         cudaFuncAttributeMaxDynamicSharedMemorySize, SM_G2);
    cudaFuncSetAttribute((const void*)gemm_kv_k,
                         cudaFuncAttributeMaxDynamicSharedMemorySize, SM_KV);
    cudaFuncSetAttribute(tail_k, cudaFuncAttributeMaxDynamicSharedMemorySize, TAIL_SMEM);

    const int NB_M  = (MTOT + 255) / 256;
    const int NB_G  = (MTOT + 127) / 128;   // 3907
    const dim3 GB_E((E_ + 255) / 256, T_);
    const int NB_AG = (MTOT * 8 + 255) / 256;

    // CSR build
    init_k  <<<NB_M, 256>>>(degcnt);
    pass1_k <<<GB_E, 256>>>(degcnt, edge_index, edge_weight);
    scan1_k <<<NSCAN, 256>>>(degcnt, offs, bsum);
    scan2_k <<<1, 128>>>(bsum, NSCAN);
    scan3_k <<<NB_M, 256>>>(offs, offw, bsum, degcnt, deg);
    scatter_k<<<GB_E, 256>>>(edge_index, edge_weight, deg, offw, bucket);

    // layer 1
    gemm1_ca_k<<<NB_G, 256, SM_G1>>>(x, gcn1_w, hwh);
    agg2_k<<<NB_AG, 256>>>(bucket, offs, offw, deg, hwh, h1);

    // layer 2
    gemm2_k<<<NB_G, 256, SM_G2>>>(h1, gcn2_w, gcn1_b, hwh);
    agg2_k<<<NB_AG, 256>>>(bucket, offs, offw, deg, hwh, h2);

    // merged K+V projection (te9 fused into A-load)
    gemm_kv_k<<<NB_G, 512, SM_KV>>>(h2, in_proj_w + 64 * 64, gcn2_b,
                                    in_proj_b + 64, global_idx, gk, gv, te9);

    tail_k<<<296, TAIL_WARPS * 32, TAIL_SMEM>>>(in_proj_w, in_proj_b, out_proj_w, out_proj_b,
                                                w1, w2, w3, w4, ln1_g, ln1_b, ln2_g, ln2_b,
                                                fc_w, fc_b, te9, gk, gv, out);
}

// round 14
// speedup vs baseline: 1.0047x; 1.0047x over previous
#include <cuda_runtime.h>
#include <cuda_fp16.h>
#include <cstdint>

#define T_   10
#define N_   50000
#define R_   50000
#define DIN_ 128
#define D_   64
#define H_   4
#define E_   400000
#define MTOT (T_ * N_)   // 500000
#define SCAN_BLK 4096
#define NSCAN ((MTOT + SCAN_BLK - 1) / SCAN_BLK)   // 123

// ---------------- scratch ----------------
__device__ float2 g_degcnt[(size_t)MTOT];
__device__ float  g_deg[(size_t)MTOT];
__device__ int    g_offs[(size_t)MTOT];
__device__ int    g_offw[(size_t)MTOT];
__device__ int    g_bsum[256];
__device__ int2   g_bucket[(size_t)T_ * E_];
__device__ __half g_hwh[(size_t)MTOT * D_];
__device__ __half g_h1 [(size_t)MTOT * D_];
__device__ __half g_h2 [(size_t)MTOT * D_];
__device__ __half g_k  [(size_t)R_ * T_ * D_];
__device__ __half g_v  [(size_t)R_ * T_ * D_];
__device__ float  g_te9[(size_t)R_ * D_];

// ---------------- init / degree+count (fused vector RED) ----------------
__global__ void init_k(float2* degcnt) {
    int i = blockIdx.x * blockDim.x + threadIdx.x;
    if (i < MTOT) degcnt[i] = make_float2(1.0f, 0.0f);
}
__global__ void pass1_k(float2* degcnt, const int* __restrict__ edge_index,
                        const float* __restrict__ ew) {
    int t = blockIdx.y;
    int e = blockIdx.x * blockDim.x + threadIdx.x;
    if (e < E_) {
        int d = __ldg(edge_index + (size_t)t * 2 * E_ + E_ + e);
        float w = __ldg(ew + (size_t)t * E_ + e);
        float* p = (float*)&degcnt[t * N_ + d];
        asm volatile("red.global.add.v2.f32 [%0], {%1,%2};"
                     :: "l"(p), "f"(w), "f"(1.0f) : "memory");
    }
}

// ---------------- scan ----------------
__global__ void scan1_k(const float2* __restrict__ degcnt, int* __restrict__ offs,
                        int* __restrict__ bsum) {
    __shared__ int ts[256];
    int b = blockIdx.x, tid = threadIdx.x;
    int base = b * SCAN_BLK + tid * 16;
    int v[16]; int s = 0;
#pragma unroll
    for (int i = 0; i < 16; i++) {
        int idx = base + i;
        v[i] = (idx < MTOT) ? (int)__ldg(&degcnt[idx].y) : 0;
        s += v[i];
    }
    ts[tid] = s;
    __syncthreads();
    for (int off = 1; off < 256; off <<= 1) {
        int x = (tid >= off) ? ts[tid - off] : 0;
        __syncthreads();
        ts[tid] += x;
        __syncthreads();
    }
    int excl = ts[tid] - s;
    if (tid == 255) bsum[b] = ts[255];
    int run = excl;
#pragma unroll
    for (int i = 0; i < 16; i++) {
        int idx = base + i;
        if (idx < MTOT) offs[idx] = run;
        run += v[i];
    }
}
__global__ void scan2_k(int* bsum, int nb) {
    __shared__ int s[128];
    int tid = threadIdx.x;
    int v = (tid < nb) ? bsum[tid] : 0;
    s[tid] = v;
    __syncthreads();
    for (int off = 1; off < 128; off <<= 1) {
        int x = (tid >= off) ? s[tid - off] : 0;
        __syncthreads();
        s[tid] += x;
        __syncthreads();
    }
    if (tid < nb) bsum[tid] = s[tid] - v;
}
__global__ void scan3_k(int* __restrict__ offs, int* __restrict__ offw,
                        const int* __restrict__ bsum, const float2* __restrict__ degcnt,
                        float* __restrict__ dinv) {
    int i = blockIdx.x * blockDim.x + threadIdx.x;
    if (i < MTOT) {
        int v = offs[i] + bsum[i >> 12];
        offs[i] = v;
        offw[i] = v;
        dinv[i] = rsqrtf(__ldg(&degcnt[i].x));
    }
}

// ---------------- scatter edges into CSR buckets ----------------
__global__ void scatter_k(const int* __restrict__ edge_index, const float* __restrict__ ew,
                          const float* __restrict__ dinv, int* __restrict__ offw,
                          int2* __restrict__ bucket) {
    int t = blockIdx.y;
    int e = blockIdx.x * blockDim.x + threadIdx.x;
    if (e >= E_) return;
    const int* src = edge_index + (size_t)t * 2 * E_;
    int s = __ldg(src + e), d = __ldg(src + E_ + e);
    float w = __ldg(ew + (size_t)t * E_ + e);
    float c = __ldg(dinv + t * N_ + s) * w * __ldg(dinv + t * N_ + d);
    int pos = atomicAdd(&offw[t * N_ + d], 1);
    bucket[pos] = make_int2(s, __float_as_int(c));
}

// ---------------- gather aggregation (fp16 src, fp32 acc, fp16 out, 4x edge ILP) ----------------
__device__ __forceinline__ void acc_half8(float4& a0, float4& a1, float c, uint4 raw) {
    const __half2* h = (const __half2*)&raw;
    float2 f0 = __half22float2(h[0]);
    float2 f1 = __half22float2(h[1]);
    float2 f2 = __half22float2(h[2]);
    float2 f3 = __half22float2(h[3]);
    a0.x = fmaf(c, f0.x, a0.x); a0.y = fmaf(c, f0.y, a0.y);
    a0.z = fmaf(c, f1.x, a0.z); a0.w = fmaf(c, f1.y, a0.w);
    a1.x = fmaf(c, f2.x, a1.x); a1.y = fmaf(c, f2.y, a1.y);
    a1.z = fmaf(c, f3.x, a1.z); a1.w = fmaf(c, f3.y, a1.w);
}

__global__ void agg2_k(const int2* __restrict__ bucket, const int* __restrict__ offs,
                       const int* __restrict__ offw, const float* __restrict__ dinv,
                       const __half* __restrict__ hwh, __half* __restrict__ out) {
    int idx = blockIdx.x * blockDim.x + threadIdx.x;
    int node = idx >> 3, sub = idx & 7;
    if (node >= MTOT) return;
    long long tb = (long long)(node / N_) * N_;
    float di = __ldg(dinv + node);
    float s2 = di * di;
    float4 acc0 = make_float4(0.f, 0.f, 0.f, 0.f);
    float4 acc1 = make_float4(0.f, 0.f, 0.f, 0.f);
    uint4 sv = __ldg((const uint4*)(hwh + (size_t)node * 64) + sub);
    acc_half8(acc0, acc1, s2, sv);
    int p = __ldg(offs + node), e = __ldg(offw + node);
    for (; p + 4 <= e; p += 4) {
        int2 e0 = __ldg(bucket + p);
        int2 e1 = __ldg(bucket + p + 1);
        int2 e2 = __ldg(bucket + p + 2);
        int2 e3 = __ldg(bucket + p + 3);
        uint4 g0 = __ldg((const uint4*)(hwh + (size_t)(tb + e0.x) * 64) + sub);
        uint4 g1 = __ldg((const uint4*)(hwh + (size_t)(tb + e1.x) * 64) + sub);
        uint4 g2 = __ldg((const uint4*)(hwh + (size_t)(tb + e2.x) * 64) + sub);
        uint4 g3 = __ldg((const uint4*)(hwh + (size_t)(tb + e3.x) * 64) + sub);
        acc_half8(acc0, acc1, __int_as_float(e0.y), g0);
        acc_half8(acc0, acc1, __int_as_float(e1.y), g1);
        acc_half8(acc0, acc1, __int_as_float(e2.y), g2);
        acc_half8(acc0, acc1, __int_as_float(e3.y), g3);
    }
    for (; p + 2 <= e; p += 2) {
        int2 e0 = __ldg(bucket + p);
        int2 e1 = __ldg(bucket + p + 1);
        uint4 g0 = __ldg((const uint4*)(hwh + (size_t)(tb + e0.x) * 64) + sub);
        uint4 g1 = __ldg((const uint4*)(hwh + (size_t)(tb + e1.x) * 64) + sub);
        acc_half8(acc0, acc1, __int_as_float(e0.y), g0);
        acc_half8(acc0, acc1, __int_as_float(e1.y), g1);
    }
    if (p < e) {
        int2 ed = __ldg(bucket + p);
        uint4 gv = __ldg((const uint4*)(hwh + (size_t)(tb + ed.x) * 64) + sub);
        acc_half8(acc0, acc1, __int_as_float(ed.y), gv);
    }
    __half2 h0 = __floats2half2_rn(acc0.x, acc0.y);
    __half2 h1 = __floats2half2_rn(acc0.z, acc0.w);
    __half2 h2 = __floats2half2_rn(acc1.x, acc1.y);
    __half2 h3 = __floats2half2_rn(acc1.z, acc1.w);
    uint4 pk;
    pk.x = *(unsigned*)&h0; pk.y = *(unsigned*)&h1;
    pk.z = *(unsigned*)&h2; pk.w = *(unsigned*)&h3;
    ((uint4*)(out + (size_t)node * 64))[sub] = pk;
}

// ---------------- tf32 helpers ----------------
__device__ __forceinline__ void mma_tf32(float* c, unsigned a0, unsigned a1,
                                         unsigned a2, unsigned a3,
                                         unsigned b0, unsigned b1) {
    asm volatile(
        "mma.sync.aligned.m16n8k8.row.col.f32.tf32.tf32.f32 "
        "{%0,%1,%2,%3}, {%4,%5,%6,%7}, {%8,%9}, {%0,%1,%2,%3};"
        : "+f"(c[0]), "+f"(c[1]), "+f"(c[2]), "+f"(c[3])
        : "r"(a0), "r"(a1), "r"(a2), "r"(a3), "r"(b0), "r"(b1));
}
__device__ __forceinline__ void split_tf32(float f, unsigned& hi, unsigned& lo) {
    unsigned u = __float_as_uint(f) & 0xFFFFE000u;
    hi = u;
    lo = __float_as_uint(f - __uint_as_float(u));
}

__device__ __forceinline__ float4 load_h4_relu(const __half* p, const float* bias, int boff) {
    __half2 a = __ldg((const __half2*)p);
    __half2 b = __ldg((const __half2*)p + 1);
    float2 lo = __half22float2(a), hi = __half22float2(b);
    float4 bb = *(const float4*)(bias + boff);
    float4 v;
    v.x = fmaxf(lo.x + bb.x, 0.f);
    v.y = fmaxf(lo.y + bb.y, 0.f);
    v.z = fmaxf(hi.x + bb.z, 0.f);
    v.w = fmaxf(hi.y + bb.w, 0.f);
    return v;
}

// ---------------- layer-1 GEMM: cp.async 4-stage, fp32 in, fp16 out ----------------
__global__ void __launch_bounds__(256, 2)
gemm1_ca_k(const float* __restrict__ A, const float* __restrict__ Wsrc,
           __half* __restrict__ hwh) {
    constexpr int K = 128, BM = 128, BK = 32, NT = 4;
    constexpr int WPAD = K + 4;
    constexpr int APAD = BK + 4;

    extern __shared__ float sm[];
    float* Wsh = sm;
    float* Ash = sm + 64 * WPAD;

    const int tid = threadIdx.x;
    const int wid = tid >> 5, lane = tid & 31;
    const int warp_m = wid & 3, warp_n = wid >> 2;
    const int lg = lane >> 2, lt = lane & 3;
    const long long row0 = (long long)blockIdx.x * BM;

#pragma unroll
    for (int kt = 0; kt < NT; kt++) {
        float* dstbase = Ash + kt * BM * APAD;
#pragma unroll
        for (int it = 0; it < 4; it++) {
            int idx = it * 256 + tid;
            int r = idx >> 3, kq = idx & 7;
            long long grow = row0 + r;
            long long srow = (grow < MTOT) ? grow : 0;
            const float* src = A + srow * K + kt * BK + kq * 4;
            unsigned dst = (unsigned)__cvta_generic_to_shared(dstbase + r * APAD + kq * 4);
            int nbytes = (grow < MTOT) ? 16 : 0;
            asm volatile("cp.async.cg.shared.global [%0], [%1], 16, %2;"
                         :: "r"(dst), "l"(src), "r"(nbytes) : "memory");
        }
        asm volatile("cp.async.commit_group;" ::: "memory");
    }

    for (int i = tid * 4; i < 64 * K; i += 256 * 4) {
        int n = i / K, k = i % K;
        float4 w = *(const float4*)(Wsrc + n * K + k);
        *(float4*)(Wsh + n * WPAD + k) = w;
    }

    float c[2][4][4];
#pragma unroll
    for (int mt = 0; mt < 2; mt++)
#pragma unroll
        for (int nt = 0; nt < 4; nt++)
#pragma unroll
            for (int i = 0; i < 4; i++) c[mt][nt][i] = 0.f;

#pragma unroll
    for (int kt = 0; kt < NT; kt++) {
        if (kt == 0)      asm volatile("cp.async.wait_group 3;" ::: "memory");
        else if (kt == 1) asm volatile("cp.async.wait_group 2;" ::: "memory");
        else if (kt == 2) asm volatile("cp.async.wait_group 1;" ::: "memory");
        else              asm volatile("cp.async.wait_group 0;" ::: "memory");
        __syncthreads();
        const float* As = Ash + kt * BM * APAD;
#pragma unroll
        for (int ks = 0; ks < 4; ks++) {
            const int k0 = ks * 8 + lt;
            unsigned ahi[2][4], alo[2][4];
#pragma unroll
            for (int mt = 0; mt < 2; mt++) {
                int ar = warp_m * 32 + mt * 16 + lg;
                float f0 = As[ar * APAD + k0];
                float f1 = As[(ar + 8) * APAD + k0];
                float f2 = As[ar * APAD + k0 + 4];
                float f3 = As[(ar + 8) * APAD + k0 + 4];
                split_tf32(f0, ahi[mt][0], alo[mt][0]);
                split_tf32(f1, ahi[mt][1], alo[mt][1]);
                split_tf32(f2, ahi[mt][2], alo[mt][2]);
                split_tf32(f3, ahi[mt][3], alo[mt][3]);
            }
            unsigned bhi[4][2], blo[4][2];
#pragma unroll
            for (int nt = 0; nt < 4; nt++) {
                int bn = warp_n * 32 + nt * 8 + lg;
                float g0 = Wsh[bn * WPAD + kt * BK + k0];
                float g1 = Wsh[bn * WPAD + kt * BK + k0 + 4];
                split_tf32(g0, bhi[nt][0], blo[nt][0]);
                split_tf32(g1, bhi[nt][1], blo[nt][1]);
            }
#pragma unroll
            for (int mt = 0; mt < 2; mt++)
#pragma unroll
                for (int nt = 0; nt < 4; nt++) {
                    mma_tf32(c[mt][nt], ahi[mt][0], ahi[mt][1], ahi[mt][2], ahi[mt][3],
                             bhi[nt][0], bhi[nt][1]);
                    mma_tf32(c[mt][nt], alo[mt][0], alo[mt][1], alo[mt][2], alo[mt][3],
                             bhi[nt][0], bhi[nt][1]);
                    mma_tf32(c[mt][nt], ahi[mt][0], ahi[mt][1], ahi[mt][2], ahi[mt][3],
                             blo[nt][0], blo[nt][1]);
                }
        }
    }

#pragma unroll
    for (int mt = 0; mt < 2; mt++) {
        long long r_lo = row0 + warp_m * 32 + mt * 16 + lg;
#pragma unroll
        for (int half = 0; half < 2; half++) {
            long long r = r_lo + half * 8;
            if (r >= MTOT) continue;
#pragma unroll
            for (int nt = 0; nt < 4; nt++) {
                int col = warp_n * 32 + nt * 8 + 2 * lt;
                *(__half2*)(hwh + r * 64 + col) =
                    __floats2half2_rn(c[mt][nt][half * 2 + 0], c[mt][nt][half * 2 + 1]);
            }
        }
    }
}

// ---------------- layer-2 GEMM (K=64, fp16 A with relu(A+b) on load, fp16 out) ----------------
__global__ void __launch_bounds__(256, 2)
gemm2_k(const __half* __restrict__ A, const float* __restrict__ Wsrc,
        const float* __restrict__ abias, __half* __restrict__ hwh) {
    constexpr int K = 64, BM = 128, BK = 32, NT = 2;
    constexpr int WPAD = K + 4;
    constexpr int APAD = BK + 4;

    extern __shared__ float sm[];
    float* Wsh = sm;
    float* Ash = sm + 64 * WPAD;

    const int tid = threadIdx.x;
    const int wid = tid >> 5, lane = tid & 31;
    const int warp_m = wid & 3, warp_n = wid >> 2;
    const int lg = lane >> 2, lt = lane & 3;
    const long long row0 = (long long)blockIdx.x * BM;

    for (int i = tid * 4; i < 64 * K; i += 256 * 4) {
        int n = i / K, k = i % K;
        float4 w = *(const float4*)(Wsrc + n * K + k);
        *(float4*)(Wsh + n * WPAD + k) = w;
    }

    float4 areg[4];
    auto lda = [&](int kt) {
#pragma unroll
        for (int it = 0; it < 4; it++) {
            int idx = it * 256 + tid;
            int r = idx >> 3, kq = idx & 7;
            long long grow = row0 + r;
            float4 v = make_float4(0.f, 0.f, 0.f, 0.f);
            if (grow < MTOT)
                v = load_h4_relu(A + grow * K + kt * BK + kq * 4, abias, kt * BK + kq * 4);
            areg[it] = v;
        }
    };
    auto sts = [&](int buf) {
        float* dst = Ash + buf * BM * APAD;
#pragma unroll
        for (int it = 0; it < 4; it++) {
            int idx = it * 256 + tid;
            int r = idx >> 3, kq = idx & 7;
            *(float4*)(dst + r * APAD + kq * 4) = areg[it];
        }
    };

    float c[2][4][4];
#pragma unroll
    for (int mt = 0; mt < 2; mt++)
#pragma unroll
        for (int nt = 0; nt < 4; nt++)
#pragma unroll
            for (int i = 0; i < 4; i++) c[mt][nt][i] = 0.f;

    lda(0);
    sts(0);

    for (int kt = 0; kt < NT; kt++) {
        __syncthreads();
        if (kt + 1 < NT) lda(kt + 1);
        const float* As = Ash + (kt & 1) * BM * APAD;
#pragma unroll
        for (int ks = 0; ks < 4; ks++) {
            const int k0 = ks * 8 + lt;
            unsigned ahi[2][4], alo[2][4];
#pragma unroll
            for (int mt = 0; mt < 2; mt++) {
                int ar = warp_m * 32 + mt * 16 + lg;
                float f0 = As[ar * APAD + k0];
                float f1 = As[(ar + 8) * APAD + k0];
                float f2 = As[ar * APAD + k0 + 4];
                float f3 = As[(ar + 8) * APAD + k0 + 4];
                split_tf32(f0, ahi[mt][0], alo[mt][0]);
                split_tf32(f1, ahi[mt][1], alo[mt][1]);
                split_tf32(f2, ahi[mt][2], alo[mt][2]);
                split_tf32(f3, ahi[mt][3], alo[mt][3]);
            }
            unsigned bhi[4][2], blo[4][2];
#pragma unroll
            for (int nt = 0; nt < 4; nt++) {
                int bn = warp_n * 32 + nt * 8 + lg;
                float g0 = Wsh[bn * WPAD + kt * BK + k0];
                float g1 = Wsh[bn * WPAD + kt * BK + k0 + 4];
                split_tf32(g0, bhi[nt][0], blo[nt][0]);
                split_tf32(g1, bhi[nt][1], blo[nt][1]);
            }
#pragma unroll
            for (int mt = 0; mt < 2; mt++)
#pragma unroll
                for (int nt = 0; nt < 4; nt++) {
                    mma_tf32(c[mt][nt], ahi[mt][0], ahi[mt][1], ahi[mt][2], ahi[mt][3],
                             bhi[nt][0], bhi[nt][1]);
                    mma_tf32(c[mt][nt], alo[mt][0], alo[mt][1], alo[mt][2], alo[mt][3],
                             bhi[nt][0], bhi[nt][1]);
                    mma_tf32(c[mt][nt], ahi[mt][0], ahi[mt][1], ahi[mt][2], ahi[mt][3],
                             blo[nt][0], blo[nt][1]);
                }
        }
        if (kt + 1 < NT) sts((kt + 1) & 1);
    }

#pragma unroll
    for (int mt = 0; mt < 2; mt++) {
        long long r_lo = row0 + warp_m * 32 + mt * 16 + lg;
#pragma unroll
        for (int half = 0; half < 2; half++) {
            long long r = r_lo + half * 8;
            if (r >= MTOT) continue;
#pragma unroll
            for (int nt = 0; nt < 4; nt++) {
                int col = warp_n * 32 + nt * 8 + 2 * lt;
                *(__half2*)(hwh + r * 64 + col) =
                    __floats2half2_rn(c[mt][nt][half * 2 + 0], c[mt][nt][half * 2 + 1]);
            }
        }
    }
}

// ---------------- merged K+V projection GEMM (fp16 A in, fp16 scatter out) ----------------
__global__ void __launch_bounds__(512, 1)
gemm_kv_k(const __half* __restrict__ A, const float* __restrict__ Wsrc,
          const float* __restrict__ abias, const float* __restrict__ ebias,
          const int* __restrict__ gidx, __half* __restrict__ gK, __half* __restrict__ gV) {
    constexpr int K = 64, BM = 128, BK = 32, NT = 2;
    constexpr int WPAD = K + 4;
    constexpr int APAD = BK + 4;

    extern __shared__ float sm[];
    float* Wsh = sm;
    float* Ash = sm + 128 * WPAD;

    const int tid = threadIdx.x;
    const int wid = tid >> 5, lane = tid & 31;
    const int warp_m = wid & 3, warp_n = wid >> 2;
    const int lg = lane >> 2, lt = lane & 3;
    const long long row0 = (long long)blockIdx.x * BM;

    for (int i = tid * 4; i < 128 * K; i += 512 * 4) {
        int n = i / K, k = i % K;
        float4 w = *(const float4*)(Wsrc + n * K + k);
        *(float4*)(Wsh + n * WPAD + k) = w;
    }

    float4 areg[2];
    auto lda = [&](int kt) {
#pragma unroll
        for (int it = 0; it < 2; it++) {
            int idx = it * 512 + tid;
            int r = idx >> 3, kq = idx & 7;
            long long grow = row0 + r;
            float4 v = make_float4(0.f, 0.f, 0.f, 0.f);
            if (grow < MTOT)
                v = load_h4_relu(A + grow * K + kt * BK + kq * 4, abias, kt * BK + kq * 4);
            areg[it] = v;
        }
    };
    auto sts = [&](int buf) {
        float* dst = Ash + buf * BM * APAD;
#pragma unroll
        for (int it = 0; it < 2; it++) {
            int idx = it * 512 + tid;
            int r = idx >> 3, kq = idx & 7;
            *(float4*)(dst + r * APAD + kq * 4) = areg[it];
        }
    };

    float c[2][4][4];
#pragma unroll
    for (int mt = 0; mt < 2; mt++)
#pragma unroll
        for (int nt = 0; nt < 4; nt++)
#pragma unroll
            for (int i = 0; i < 4; i++) c[mt][nt][i] = 0.f;

    lda(0);
    sts(0);

    for (int kt = 0; kt < NT; kt++) {
        __syncthreads();
        if (kt + 1 < NT) lda(kt + 1);
        const float* As = Ash + (kt & 1) * BM * APAD;
#pragma unroll
        for (int ks = 0; ks < 4; ks++) {
            const int k0 = ks * 8 + lt;
            unsigned ahi[2][4], alo[2][4];
#pragma unroll
            for (int mt = 0; mt < 2; mt++) {
                int ar = warp_m * 32 + mt * 16 + lg;
                float f0 = As[ar * APAD + k0];
                float f1 = As[(ar + 8) * APAD + k0];
                float f2 = As[ar * APAD + k0 + 4];
                float f3 = As[(ar + 8) * APAD + k0 + 4];
                split_tf32(f0, ahi[mt][0], alo[mt][0]);
                split_tf32(f1, ahi[mt][1], alo[mt][1]);
                split_tf32(f2, ahi[mt][2], alo[mt][2]);
                split_tf32(f3, ahi[mt][3], alo[mt][3]);
            }
            unsigned bhi[4][2], blo[4][2];
#pragma unroll
            for (int nt = 0; nt < 4; nt++) {
                int bn = warp_n * 32 + nt * 8 + lg;
                float g0 = Wsh[bn * WPAD + kt * BK + k0];
                float g1 = Wsh[bn * WPAD + kt * BK + k0 + 4];
                split_tf32(g0, bhi[nt][0], blo[nt][0]);
                split_tf32(g1, bhi[nt][1], blo[nt][1]);
            }
#pragma unroll
            for (int mt = 0; mt < 2; mt++)
#pragma unroll
                for (int nt = 0; nt < 4; nt++) {
                    mma_tf32(c[mt][nt], ahi[mt][0], ahi[mt][1], ahi[mt][2], ahi[mt][3],
                             bhi[nt][0], bhi[nt][1]);
                    mma_tf32(c[mt][nt], alo[mt][0], alo[mt][1], alo[mt][2], alo[mt][3],
                             bhi[nt][0], bhi[nt][1]);
                    mma_tf32(c[mt][nt], ahi[mt][0], ahi[mt][1], ahi[mt][2], ahi[mt][3],
                             blo[nt][0], blo[nt][1]);
                }
        }
        if (kt + 1 < NT) sts((kt + 1) & 1);
    }

#pragma unroll
    for (int mt = 0; mt < 2; mt++) {
        long long r_lo = row0 + warp_m * 32 + mt * 16 + lg;
#pragma unroll
        for (int half = 0; half < 2; half++) {
            long long r = r_lo + half * 8;
            if (r >= MTOT) continue;
            unsigned rr = (unsigned)r;
            unsigned t = rr / (unsigned)N_;
            unsigned n = rr - t * (unsigned)N_;
            int ridx = __ldg(gidx + (size_t)t * R_ + n);
            size_t rowoff = ((size_t)ridx * T_ + t) * 64;
#pragma unroll
            for (int nt = 0; nt < 4; nt++) {
                int col = warp_n * 32 + nt * 8 + 2 * lt;
                float2 b = *(const float2*)(ebias + col);
                __half* base = (col < 64 ? gK + rowoff + col : gV + rowoff + (col - 64));
                *(__half2*)base = __floats2half2_rn(c[mt][nt][half * 2 + 0] + b.x,
                                                    c[mt][nt][half * 2 + 1] + b.y);
            }
        }
    }
}

// ---------------- te9: relu(h2[t=9] + b2) scattered by gidx (standalone) ----------------
__global__ void te9_k(const __half* __restrict__ h2, const float* __restrict__ b2,
                      const int* __restrict__ gidx, float* __restrict__ te9) {
    int idx = blockIdx.x * blockDim.x + threadIdx.x;
    if (idx >= N_ * D_) return;
    int n = idx >> 6, c = idx & 63;
    float v = fmaxf(__half2float(h2[((size_t)9 * N_ + n) * 64 + c]) + b2[c], 0.f);
    te9[(size_t)__ldg(gidx + (size_t)9 * R_ + n) * 64 + c] = v;
}

// ---------------- tail ----------------
#define TAIL_WARPS 8
#define TAIL_SMEM  ((12288 + 704 + TAIL_WARPS * 1456) * 4)

__device__ __forceinline__ float warp_sum(float v) {
#pragma unroll
    for (int off = 16; off; off >>= 1) v += __shfl_xor_sync(0xffffffffu, v, off);
    return v;
}

__global__ void tail_k(const float* __restrict__ inW, const float* __restrict__ inB,
                       const float* __restrict__ outW, const float* __restrict__ outB,
                       const float* __restrict__ w1, const float* __restrict__ w2,
                       const float* __restrict__ w3, const float* __restrict__ w4,
                       const float* __restrict__ ln1g, const float* __restrict__ ln1b,
                       const float* __restrict__ ln2g, const float* __restrict__ ln2b,
                       const float* __restrict__ fcW, const float* __restrict__ fcB,
                       const float* __restrict__ te9, const __half* __restrict__ gK,
                       const __half* __restrict__ gV, float* __restrict__ out) {
    extern __shared__ float sh[];
    float* Wq = sh;
    float* Wo = sh + 4096;
    float* Wf = sh + 8192;
    float* cv = sh + 12288;

    int tid = threadIdx.x;
    for (int i = tid; i < 4096; i += TAIL_WARPS * 32) {
        int k = i >> 6, j = i & 63;
        Wq[i] = inW[j * 64 + k];
        Wo[i] = outW[j * 64 + k];
        Wf[i] = fcW[j * 64 + k];
    }
    if (tid < 64) {
        cv[tid]       = inB[tid];
        cv[64 + tid]  = outB[tid];
        cv[128 + tid] = fcB[tid];
        cv[192 + tid] = w1[(T_ - 1) * 64 + tid];
        cv[256 + tid] = w2[(T_ - 1) * 64 + tid];
        cv[320 + tid] = ln1g[tid];
        cv[384 + tid] = ln1b[tid];
        cv[448 + tid] = w3[tid];
        cv[512 + tid] = w4[tid];
        cv[576 + tid] = ln2g[tid];
        cv[640 + tid] = ln2b[tid];
    }
    __syncthreads();

    int warp = tid >> 5, lane = tid & 31;
    float* wb   = cv + 704 + warp * 1456;
    float* pvec = wb;
    float* pq   = wb + 64;
    float* kb   = wb + 128;
    float* vb   = wb + 768;
    float* sc   = wb + 1408;

    int gw = blockIdx.x * TAIL_WARPS + warp;
    int nw = gridDim.x * TAIL_WARPS;

    for (int r = gw; r < R_; r += nw) {
        pvec[lane]      = te9[(size_t)r * 64 + lane];
        pvec[lane + 32] = te9[(size_t)r * 64 + lane + 32];
        const __half2* kr = (const __half2*)(gK + (size_t)r * 640);
        const __half2* vr = (const __half2*)(gV + (size_t)r * 640);
        for (int i = lane; i < 320; i += 32) {
            *(float2*)(kb + 2 * i) = __half22float2(__ldg(kr + i));
            *(float2*)(vb + 2 * i) = __half22float2(__ldg(vr + i));
        }
        __syncwarp();

        float q0 = cv[lane], q1 = cv[lane + 32];
        for (int k = 0; k < 64; k++) {
            float xv = pvec[k];
            q0 = fmaf(xv, Wq[k * 64 + lane], q0);
            q1 = fmaf(xv, Wq[k * 64 + lane + 32], q1);
        }
        pq[lane] = q0; pq[lane + 32] = q1;
        __syncwarp();

        for (int p = lane; p < H_ * T_; p += 32) {
            int h = p / T_, tt = p - h * T_;
            const float* qh = pq + h * 16;
            const float* kh = kb + tt * 64 + h * 16;
            float s = 0.f;
#pragma unroll
            for (int d = 0; d < 16; d++) s = fmaf(qh[d], kh[d], s);
            sc[p] = s * 0.25f;
        }
        __syncwarp();

        if (lane < H_) {
            float mx = -1e30f;
#pragma unroll
            for (int tt = 0; tt < T_; tt++) mx = fmaxf(mx, sc[lane * T_ + tt]);
            float sm = 0.f;
#pragma unroll
            for (int tt = 0; tt < T_; tt++) {
                float ev = __expf(sc[lane * T_ + tt] - mx);
                sc[lane * T_ + tt] = ev; sm += ev;
            }
            float inv = 1.f / sm;
#pragma unroll
            for (int tt = 0; tt < T_; tt++) sc[lane * T_ + tt] *= inv;
        }
        __syncwarp();

        int h0 = lane >> 4, h1 = (lane + 32) >> 4;
        float a0 = 0.f, a1 = 0.f;
#pragma unroll
        for (int tt = 0; tt < T_; tt++) {
            a0 = fmaf(sc[h0 * T_ + tt], vb[tt * 64 + lane], a0);
            a1 = fmaf(sc[h1 * T_ + tt], vb[tt * 64 + lane + 32], a1);
        }
        pq[lane] = a0; pq[lane + 32] = a1;
        __syncwarp();

        float o0 = cv[64 + lane], o1 = cv[64 + lane + 32];
        for (int k = 0; k < 64; k++) {
            float xv = pq[k];
            o0 = fmaf(xv, Wo[k * 64 + lane], o0);
            o1 = fmaf(xv, Wo[k * 64 + lane + 32], o1);
        }

        float y0 = cv[192 + lane] * pvec[lane] + cv[256 + lane] * o0;
        float y1 = cv[192 + lane + 32] * pvec[lane + 32] + cv[256 + lane + 32] * o1;
        float mu = warp_sum(y0 + y1) * (1.f / 64.f);
        float d0 = y0 - mu, d1 = y1 - mu;
        float var = warp_sum(d0 * d0 + d1 * d1) * (1.f / 64.f);
        float rs = rsqrtf(var + 1e-5f);
        float f0 = d0 * rs * cv[320 + lane] + cv[384 + lane];
        float f1 = d1 * rs * cv[320 + lane + 32] + cv[384 + lane + 32];
        __syncwarp();
        pvec[lane] = f0; pvec[lane + 32] = f1;
        __syncwarp();

        float u0 = cv[128 + lane], u1 = cv[128 + lane + 32];
        for (int k = 0; k < 64; k++) {
            float xv = pvec[k];
            u0 = fmaf(xv, Wf[k * 64 + lane], u0);
            u1 = fmaf(xv, Wf[k * 64 + lane + 32], u1);
        }
        float z0 = cv[448 + lane] * f0 + cv[512 + lane] * u0;
        float z1 = cv[448 + lane + 32] * f1 + cv[512 + lane + 32] * u1;
        float mu2 = warp_sum(z0 + z1) * (1.f / 64.f);
        float e0 = z0 - mu2, e1 = z1 - mu2;
        float var2 = warp_sum(e0 * e0 + e1 * e1) * (1.f / 64.f);
        float rs2 = rsqrtf(var2 + 1e-5f);
        out[(size_t)r * 64 + lane]      = e0 * rs2 * cv[576 + lane] + cv[640 + lane];
        out[(size_t)r * 64 + lane + 32] = e1 * rs2 * cv[576 + lane + 32] + cv[640 + lane + 32];
        __syncwarp();
    }
}

// ---------------- launch ----------------
extern "C" void kernel_launch(void* const* d_in, const int* in_sizes, int n_in,
                              void* d_out, int out_size) {
    const float* x          = (const float*)d_in[0];
    const int*   edge_index = (const int*)  d_in[1];
    const float* edge_weight= (const float*)d_in[2];
    const int*   global_idx = (const int*)  d_in[3];
    const float* gcn1_w     = (const float*)d_in[4];
    const float* gcn1_b     = (const float*)d_in[5];
    const float* gcn2_w     = (const float*)d_in[6];
    const float* gcn2_b     = (const float*)d_in[7];
    const float* in_proj_w  = (const float*)d_in[8];
    const float* in_proj_b  = (const float*)d_in[9];
    const float* out_proj_w = (const float*)d_in[10];
    const float* out_proj_b = (const float*)d_in[11];
    const float* w1         = (const float*)d_in[12];
    const float* w2         = (const float*)d_in[13];
    const float* w3         = (const float*)d_in[14];
    const float* w4         = (const float*)d_in[15];
    const float* ln1_g      = (const float*)d_in[16];
    const float* ln1_b      = (const float*)d_in[17];
    const float* ln2_g      = (const float*)d_in[18];
    const float* ln2_b      = (const float*)d_in[19];
    const float* fc_w       = (const float*)d_in[20];
    const float* fc_b       = (const float*)d_in[21];
    float* out = (float*)d_out;

    float *deg, *te9;
    float2* degcnt;
    __half *hwh, *h1, *h2, *gk, *gv;
    int *offs, *offw, *bsum;
    int2* bucket;
    cudaGetSymbolAddress((void**)&degcnt, g_degcnt);
    cudaGetSymbolAddress((void**)&deg,  g_deg);
    cudaGetSymbolAddress((void**)&offs, g_offs);
    cudaGetSymbolAddress((void**)&offw, g_offw);
    cudaGetSymbolAddress((void**)&bsum, g_bsum);
    cudaGetSymbolAddress((void**)&bucket, g_bucket);
    cudaGetSymbolAddress((void**)&hwh, g_hwh);
    cudaGetSymbolAddress((void**)&h1,  g_h1);
    cudaGetSymbolAddress((void**)&h2,  g_h2);
    cudaGetSymbolAddress((void**)&gk,  g_k);
    cudaGetSymbolAddress((void**)&gv,  g_v);
    cudaGetSymbolAddress((void**)&te9, g_te9);

    const int SM_G1 = (64 * (128 + 4) + 4 * 128 * 36) * 4;   // 107520
    const int SM_G2 = (64 * (64 + 4)  + 2 * 128 * 36) * 4;   // 54272
    const int SM_KV = (128 * (64 + 4) + 2 * 128 * 36) * 4;   // 71680
    cudaFuncSetAttribute((const void*)gemm1_ca_k,
                         cudaFuncAttributeMaxDynamicSharedMemorySize, SM_G1);
    cudaFuncSetAttribute((const void*)gemm2_k,
                         cudaFuncAttributeMaxDynamicSharedMemorySize, SM_G2);
    cudaFuncSetAttribute((const void*)gemm_kv_k,
                         cudaFuncAttributeMaxDynamicSharedMemorySize, SM_KV);
    cudaFuncSetAttribute(tail_k, cudaFuncAttributeMaxDynamicSharedMemorySize, TAIL_SMEM);

    const int NB_M  = (MTOT + 255) / 256;
    const int NB_G  = (MTOT + 127) / 128;   // 3907
    const dim3 GB_E((E_ + 255) / 256, T_);
    const int NB_AG = (MTOT * 8 + 255) / 256;

    // CSR build
    init_k  <<<NB_M, 256>>>(degcnt);
    pass1_k <<<GB_E, 256>>>(degcnt, edge_index, edge_weight);
    scan1_k <<<NSCAN, 256>>>(degcnt, offs, bsum);
    scan2_k <<<1, 128>>>(bsum, NSCAN);
    scan3_k <<<NB_M, 256>>>(offs, offw, bsum, degcnt, deg);
    scatter_k<<<GB_E, 256>>>(edge_index, edge_weight, deg, offw, bucket);

    // layer 1
    gemm1_ca_k<<<NB_G, 256, SM_G1>>>(x, gcn1_w, hwh);
    agg2_k<<<NB_AG, 256>>>(bucket, offs, offw, deg, hwh, h1);

    // layer 2
    gemm2_k<<<NB_G, 256, SM_G2>>>(h1, gcn2_w, gcn1_b, hwh);
    agg2_k<<<NB_AG, 256>>>(bucket, offs, offw, deg, hwh, h2);

    // merged K+V projection (no te9 fusion)
    gemm_kv_k<<<NB_G, 512, SM_KV>>>(h2, in_proj_w + 64 * 64, gcn2_b,
                                    in_proj_b + 64, global_idx, gk, gv);
    te9_k<<<(N_ * D_ + 255) / 256, 256>>>(h2, gcn2_b, global_idx, te9);

    tail_k<<<296, TAIL_WARPS * 32, TAIL_SMEM>>>(in_proj_w, in_proj_b, out_proj_w, out_proj_b,
                                                w1, w2, w3, w4, ln1_g, ln1_b, ln2_g, ln2_b,
                                                fc_w, fc_b, te9, gk, gv, out);
}

// round 15
// speedup vs baseline: 1.0888x; 1.0837x over previous
#include <cuda_runtime.h>
#include <cuda_fp16.h>
#include <cstdint>

#define T_   10
#define N_   50000
#define R_   50000
#define DIN_ 128
#define D_   64
#define H_   4
#define E_   400000
#define MTOT (T_ * N_)   // 500000
#define SCAN_BLK 4096
#define NSCAN ((MTOT + SCAN_BLK - 1) / SCAN_BLK)   // 123

// ---------------- scratch ----------------
__device__ float2   g_degcnt[(size_t)MTOT];
__device__ float    g_deg[(size_t)MTOT];
__device__ int      g_offs[(size_t)MTOT];
__device__ int      g_offw[(size_t)MTOT];
__device__ int      g_bsum[256];
__device__ unsigned g_bucket[(size_t)T_ * E_];   // packed: src(16) | half(c)(16)
__device__ __half   g_hwh[(size_t)MTOT * D_];
__device__ __half   g_h1 [(size_t)MTOT * D_];
__device__ __half   g_h2 [(size_t)MTOT * D_];
__device__ __half   g_k  [(size_t)R_ * T_ * D_];
__device__ __half   g_v  [(size_t)R_ * T_ * D_];
__device__ float    g_te9[(size_t)R_ * D_];

// ---------------- init / degree+count (fused vector RED) ----------------
__global__ void init_k(float2* degcnt) {
    int i = blockIdx.x * blockDim.x + threadIdx.x;
    if (i < MTOT) degcnt[i] = make_float2(1.0f, 0.0f);
}
__global__ void pass1_k(float2* degcnt, const int* __restrict__ edge_index,
                        const float* __restrict__ ew) {
    int t = blockIdx.y;
    int e = blockIdx.x * blockDim.x + threadIdx.x;
    if (e < E_) {
        int d = __ldg(edge_index + (size_t)t * 2 * E_ + E_ + e);
        float w = __ldg(ew + (size_t)t * E_ + e);
        float* p = (float*)&degcnt[t * N_ + d];
        asm volatile("red.global.add.v2.f32 [%0], {%1,%2};"
                     :: "l"(p), "f"(w), "f"(1.0f) : "memory");
    }
}

// ---------------- scan ----------------
__global__ void scan1_k(const float2* __restrict__ degcnt, int* __restrict__ offs,
                        int* __restrict__ bsum) {
    __shared__ int ts[256];
    int b = blockIdx.x, tid = threadIdx.x;
    int base = b * SCAN_BLK + tid * 16;
    int v[16]; int s = 0;
#pragma unroll
    for (int i = 0; i < 16; i++) {
        int idx = base + i;
        v[i] = (idx < MTOT) ? (int)__ldg(&degcnt[idx].y) : 0;
        s += v[i];
    }
    ts[tid] = s;
    __syncthreads();
    for (int off = 1; off < 256; off <<= 1) {
        int x = (tid >= off) ? ts[tid - off] : 0;
        __syncthreads();
        ts[tid] += x;
        __syncthreads();
    }
    int excl = ts[tid] - s;
    if (tid == 255) bsum[b] = ts[255];
    int run = excl;
#pragma unroll
    for (int i = 0; i < 16; i++) {
        int idx = base + i;
        if (idx < MTOT) offs[idx] = run;
        run += v[i];
    }
}
__global__ void scan2_k(int* bsum, int nb) {
    __shared__ int s[128];
    int tid = threadIdx.x;
    int v = (tid < nb) ? bsum[tid] : 0;
    s[tid] = v;
    __syncthreads();
    for (int off = 1; off < 128; off <<= 1) {
        int x = (tid >= off) ? s[tid - off] : 0;
        __syncthreads();
        s[tid] += x;
        __syncthreads();
    }
    if (tid < nb) bsum[tid] = s[tid] - v;
}
__global__ void scan3_k(int* __restrict__ offs, int* __restrict__ offw,
                        const int* __restrict__ bsum, const float2* __restrict__ degcnt,
                        float* __restrict__ dinv) {
    int i = blockIdx.x * blockDim.x + threadIdx.x;
    if (i < MTOT) {
        int v = offs[i] + bsum[i >> 12];
        offs[i] = v;
        offw[i] = v;
        dinv[i] = rsqrtf(__ldg(&degcnt[i].x));
    }
}

// ---------------- scatter edges into packed CSR buckets ----------------
__global__ void scatter_k(const int* __restrict__ edge_index, const float* __restrict__ ew,
                          const float* __restrict__ dinv, int* __restrict__ offw,
                          unsigned* __restrict__ bucket) {
    int t = blockIdx.y;
    int e = blockIdx.x * blockDim.x + threadIdx.x;
    if (e >= E_) return;
    const int* src = edge_index + (size_t)t * 2 * E_;
    int s = __ldg(src + e), d = __ldg(src + E_ + e);
    float w = __ldg(ew + (size_t)t * E_ + e);
    float c = __ldg(dinv + t * N_ + s) * w * __ldg(dinv + t * N_ + d);
    int pos = atomicAdd(&offw[t * N_ + d], 1);
    unsigned ch = (unsigned)__half_as_ushort(__float2half_rn(c));
    bucket[pos] = (unsigned)s | (ch << 16);
}

// ---------------- gather aggregation (fp16 src, fp32 acc, fp16 out, 2x ILP) ----------------
__device__ __forceinline__ void acc_half8(float4& a0, float4& a1, float c, uint4 raw) {
    const __half2* h = (const __half2*)&raw;
    float2 f0 = __half22float2(h[0]);
    float2 f1 = __half22float2(h[1]);
    float2 f2 = __half22float2(h[2]);
    float2 f3 = __half22float2(h[3]);
    a0.x = fmaf(c, f0.x, a0.x); a0.y = fmaf(c, f0.y, a0.y);
    a0.z = fmaf(c, f1.x, a0.z); a0.w = fmaf(c, f1.y, a0.w);
    a1.x = fmaf(c, f2.x, a1.x); a1.y = fmaf(c, f2.y, a1.y);
    a1.z = fmaf(c, f3.x, a1.z); a1.w = fmaf(c, f3.y, a1.w);
}
__device__ __forceinline__ float bkt_c(unsigned b) {
    return __half2float(__ushort_as_half((unsigned short)(b >> 16)));
}

__global__ void agg2_k(const unsigned* __restrict__ bucket, const int* __restrict__ offs,
                       const int* __restrict__ offw, const float* __restrict__ dinv,
                       const __half* __restrict__ hwh, __half* __restrict__ out) {
    int idx = blockIdx.x * blockDim.x + threadIdx.x;
    int node = idx >> 3, sub = idx & 7;
    if (node >= MTOT) return;
    long long tb = (long long)(node / N_) * N_;
    float di = __ldg(dinv + node);
    float s2 = di * di;
    float4 acc0 = make_float4(0.f, 0.f, 0.f, 0.f);
    float4 acc1 = make_float4(0.f, 0.f, 0.f, 0.f);
    uint4 sv = __ldg((const uint4*)(hwh + (size_t)node * 64) + sub);
    acc_half8(acc0, acc1, s2, sv);
    int p = __ldg(offs + node), e = __ldg(offw + node);
    for (; p + 2 <= e; p += 2) {
        unsigned e0 = __ldg(bucket + p);
        unsigned e1 = __ldg(bucket + p + 1);
        uint4 g0 = __ldg((const uint4*)(hwh + (size_t)(tb + (e0 & 0xFFFFu)) * 64) + sub);
        uint4 g1 = __ldg((const uint4*)(hwh + (size_t)(tb + (e1 & 0xFFFFu)) * 64) + sub);
        acc_half8(acc0, acc1, bkt_c(e0), g0);
        acc_half8(acc0, acc1, bkt_c(e1), g1);
    }
    if (p < e) {
        unsigned ed = __ldg(bucket + p);
        uint4 gv = __ldg((const uint4*)(hwh + (size_t)(tb + (ed & 0xFFFFu)) * 64) + sub);
        acc_half8(acc0, acc1, bkt_c(ed), gv);
    }
    __half2 h0 = __floats2half2_rn(acc0.x, acc0.y);
    __half2 h1 = __floats2half2_rn(acc0.z, acc0.w);
    __half2 h2 = __floats2half2_rn(acc1.x, acc1.y);
    __half2 h3 = __floats2half2_rn(acc1.z, acc1.w);
    uint4 pk;
    pk.x = *(unsigned*)&h0; pk.y = *(unsigned*)&h1;
    pk.z = *(unsigned*)&h2; pk.w = *(unsigned*)&h3;
    ((uint4*)(out + (size_t)node * 64))[sub] = pk;
}

// ---------------- tf32 helpers ----------------
__device__ __forceinline__ void mma_tf32(float* c, unsigned a0, unsigned a1,
                                         unsigned a2, unsigned a3,
                                         unsigned b0, unsigned b1) {
    asm volatile(
        "mma.sync.aligned.m16n8k8.row.col.f32.tf32.tf32.f32 "
        "{%0,%1,%2,%3}, {%4,%5,%6,%7}, {%8,%9}, {%0,%1,%2,%3};"
        : "+f"(c[0]), "+f"(c[1]), "+f"(c[2]), "+f"(c[3])
        : "r"(a0), "r"(a1), "r"(a2), "r"(a3), "r"(b0), "r"(b1));
}
__device__ __forceinline__ void split_tf32(float f, unsigned& hi, unsigned& lo) {
    unsigned u = __float_as_uint(f) & 0xFFFFE000u;
    hi = u;
    lo = __float_as_uint(f - __uint_as_float(u));
}

__device__ __forceinline__ float4 load_h4_relu(const __half* p, const float* bias, int boff) {
    __half2 a = __ldg((const __half2*)p);
    __half2 b = __ldg((const __half2*)p + 1);
    float2 lo = __half22float2(a), hi = __half22float2(b);
    float4 bb = *(const float4*)(bias + boff);
    float4 v;
    v.x = fmaxf(lo.x + bb.x, 0.f);
    v.y = fmaxf(lo.y + bb.y, 0.f);
    v.z = fmaxf(hi.x + bb.z, 0.f);
    v.w = fmaxf(hi.y + bb.w, 0.f);
    return v;
}

// ---------------- layer-1 GEMM: cp.async 4-stage, fp32 in, fp16 out ----------------
__global__ void __launch_bounds__(256, 2)
gemm1_ca_k(const float* __restrict__ A, const float* __restrict__ Wsrc,
           __half* __restrict__ hwh) {
    constexpr int K = 128, BM = 128, BK = 32, NT = 4;
    constexpr int WPAD = K + 4;
    constexpr int APAD = BK + 4;

    extern __shared__ float sm[];
    float* Wsh = sm;
    float* Ash = sm + 64 * WPAD;

    const int tid = threadIdx.x;
    const int wid = tid >> 5, lane = tid & 31;
    const int warp_m = wid & 3, warp_n = wid >> 2;
    const int lg = lane >> 2, lt = lane & 3;
    const long long row0 = (long long)blockIdx.x * BM;

#pragma unroll
    for (int kt = 0; kt < NT; kt++) {
        float* dstbase = Ash + kt * BM * APAD;
#pragma unroll
        for (int it = 0; it < 4; it++) {
            int idx = it * 256 + tid;
            int r = idx >> 3, kq = idx & 7;
            long long grow = row0 + r;
            long long srow = (grow < MTOT) ? grow : 0;
            const float* src = A + srow * K + kt * BK + kq * 4;
            unsigned dst = (unsigned)__cvta_generic_to_shared(dstbase + r * APAD + kq * 4);
            int nbytes = (grow < MTOT) ? 16 : 0;
            asm volatile("cp.async.cg.shared.global [%0], [%1], 16, %2;"
                         :: "r"(dst), "l"(src), "r"(nbytes) : "memory");
        }
        asm volatile("cp.async.commit_group;" ::: "memory");
    }

    for (int i = tid * 4; i < 64 * K; i += 256 * 4) {
        int n = i / K, k = i % K;
        float4 w = *(const float4*)(Wsrc + n * K + k);
        *(float4*)(Wsh + n * WPAD + k) = w;
    }

    float c[2][4][4];
#pragma unroll
    for (int mt = 0; mt < 2; mt++)
#pragma unroll
        for (int nt = 0; nt < 4; nt++)
#pragma unroll
            for (int i = 0; i < 4; i++) c[mt][nt][i] = 0.f;

#pragma unroll
    for (int kt = 0; kt < NT; kt++) {
        if (kt == 0)      asm volatile("cp.async.wait_group 3;" ::: "memory");
        else if (kt == 1) asm volatile("cp.async.wait_group 2;" ::: "memory");
        else if (kt == 2) asm volatile("cp.async.wait_group 1;" ::: "memory");
        else              asm volatile("cp.async.wait_group 0;" ::: "memory");
        __syncthreads();
        const float* As = Ash + kt * BM * APAD;
#pragma unroll
        for (int ks = 0; ks < 4; ks++) {
            const int k0 = ks * 8 + lt;
            unsigned ahi[2][4], alo[2][4];
#pragma unroll
            for (int mt = 0; mt < 2; mt++) {
                int ar = warp_m * 32 + mt * 16 + lg;
                float f0 = As[ar * APAD + k0];
                float f1 = As[(ar + 8) * APAD + k0];
                float f2 = As[ar * APAD + k0 + 4];
                float f3 = As[(ar + 8) * APAD + k0 + 4];
                split_tf32(f0, ahi[mt][0], alo[mt][0]);
                split_tf32(f1, ahi[mt][1], alo[mt][1]);
                split_tf32(f2, ahi[mt][2], alo[mt][2]);
                split_tf32(f3, ahi[mt][3], alo[mt][3]);
            }
            unsigned bhi[4][2], blo[4][2];
#pragma unroll
            for (int nt = 0; nt < 4; nt++) {
                int bn = warp_n * 32 + nt * 8 + lg;
                float g0 = Wsh[bn * WPAD + kt * BK + k0];
                float g1 = Wsh[bn * WPAD + kt * BK + k0 + 4];
                split_tf32(g0, bhi[nt][0], blo[nt][0]);
                split_tf32(g1, bhi[nt][1], blo[nt][1]);
            }
#pragma unroll
            for (int mt = 0; mt < 2; mt++)
#pragma unroll
                for (int nt = 0; nt < 4; nt++) {
                    mma_tf32(c[mt][nt], ahi[mt][0], ahi[mt][1], ahi[mt][2], ahi[mt][3],
                             bhi[nt][0], bhi[nt][1]);
                    mma_tf32(c[mt][nt], alo[mt][0], alo[mt][1], alo[mt][2], alo[mt][3],
                             bhi[nt][0], bhi[nt][1]);
                    mma_tf32(c[mt][nt], ahi[mt][0], ahi[mt][1], ahi[mt][2], ahi[mt][3],
                             blo[nt][0], blo[nt][1]);
                }
        }
    }

#pragma unroll
    for (int mt = 0; mt < 2; mt++) {
        long long r_lo = row0 + warp_m * 32 + mt * 16 + lg;
#pragma unroll
        for (int half = 0; half < 2; half++) {
            long long r = r_lo + half * 8;
            if (r >= MTOT) continue;
#pragma unroll
            for (int nt = 0; nt < 4; nt++) {
                int col = warp_n * 32 + nt * 8 + 2 * lt;
                *(__half2*)(hwh + r * 64 + col) =
                    __floats2half2_rn(c[mt][nt][half * 2 + 0], c[mt][nt][half * 2 + 1]);
            }
        }
    }
}

// ---------------- layer-2 GEMM (K=64, fp16 A with relu(A+b) on load, fp16 out) ----------------
__global__ void __launch_bounds__(256, 2)
gemm2_k(const __half* __restrict__ A, const float* __restrict__ Wsrc,
        const float* __restrict__ abias, __half* __restrict__ hwh) {
    constexpr int K = 64, BM = 128, BK = 32, NT = 2;
    constexpr int WPAD = K + 4;
    constexpr int APAD = BK + 4;

    extern __shared__ float sm[];
    float* Wsh = sm;
    float* Ash = sm + 64 * WPAD;

    const int tid = threadIdx.x;
    const int wid = tid >> 5, lane = tid & 31;
    const int warp_m = wid & 3, warp_n = wid >> 2;
    const int lg = lane >> 2, lt = lane & 3;
    const long long row0 = (long long)blockIdx.x * BM;

    for (int i = tid * 4; i < 64 * K; i += 256 * 4) {
        int n = i / K, k = i % K;
        float4 w = *(const float4*)(Wsrc + n * K + k);
        *(float4*)(Wsh + n * WPAD + k) = w;
    }

    float4 areg[4];
    auto lda = [&](int kt) {
#pragma unroll
        for (int it = 0; it < 4; it++) {
            int idx = it * 256 + tid;
            int r = idx >> 3, kq = idx & 7;
            long long grow = row0 + r;
            float4 v = make_float4(0.f, 0.f, 0.f, 0.f);
            if (grow < MTOT)
                v = load_h4_relu(A + grow * K + kt * BK + kq * 4, abias, kt * BK + kq * 4);
            areg[it] = v;
        }
    };
    auto sts = [&](int buf) {
        float* dst = Ash + buf * BM * APAD;
#pragma unroll
        for (int it = 0; it < 4; it++) {
            int idx = it * 256 + tid;
            int r = idx >> 3, kq = idx & 7;
            *(float4*)(dst + r * APAD + kq * 4) = areg[it];
        }
    };

    float c[2][4][4];
#pragma unroll
    for (int mt = 0; mt < 2; mt++)
#pragma unroll
        for (int nt = 0; nt < 4; nt++)
#pragma unroll
            for (int i = 0; i < 4; i++) c[mt][nt][i] = 0.f;

    lda(0);
    sts(0);

    for (int kt = 0; kt < NT; kt++) {
        __syncthreads();
        if (kt + 1 < NT) lda(kt + 1);
        const float* As = Ash + (kt & 1) * BM * APAD;
#pragma unroll
        for (int ks = 0; ks < 4; ks++) {
            const int k0 = ks * 8 + lt;
            unsigned ahi[2][4], alo[2][4];
#pragma unroll
            for (int mt = 0; mt < 2; mt++) {
                int ar = warp_m * 32 + mt * 16 + lg;
                float f0 = As[ar * APAD + k0];
                float f1 = As[(ar + 8) * APAD + k0];
                float f2 = As[ar * APAD + k0 + 4];
                float f3 = As[(ar + 8) * APAD + k0 + 4];
                split_tf32(f0, ahi[mt][0], alo[mt][0]);
                split_tf32(f1, ahi[mt][1], alo[mt][1]);
                split_tf32(f2, ahi[mt][2], alo[mt][2]);
                split_tf32(f3, ahi[mt][3], alo[mt][3]);
            }
            unsigned bhi[4][2], blo[4][2];
#pragma unroll
            for (int nt = 0; nt < 4; nt++) {
                int bn = warp_n * 32 + nt * 8 + lg;
                float g0 = Wsh[bn * WPAD + kt * BK + k0];
                float g1 = Wsh[bn * WPAD + kt * BK + k0 + 4];
                split_tf32(g0, bhi[nt][0], blo[nt][0]);
                split_tf32(g1, bhi[nt][1], blo[nt][1]);
            }
#pragma unroll
            for (int mt = 0; mt < 2; mt++)
#pragma unroll
                for (int nt = 0; nt < 4; nt++) {
                    mma_tf32(c[mt][nt], ahi[mt][0], ahi[mt][1], ahi[mt][2], ahi[mt][3],
                             bhi[nt][0], bhi[nt][1]);
                    mma_tf32(c[mt][nt], alo[mt][0], alo[mt][1], alo[mt][2], alo[mt][3],
                             bhi[nt][0], bhi[nt][1]);
                    mma_tf32(c[mt][nt], ahi[mt][0], ahi[mt][1], ahi[mt][2], ahi[mt][3],
                             blo[nt][0], blo[nt][1]);
                }
        }
        if (kt + 1 < NT) sts((kt + 1) & 1);
    }

#pragma unroll
    for (int mt = 0; mt < 2; mt++) {
        long long r_lo = row0 + warp_m * 32 + mt * 16 + lg;
#pragma unroll
        for (int half = 0; half < 2; half++) {
            long long r = r_lo + half * 8;
            if (r >= MTOT) continue;
#pragma unroll
            for (int nt = 0; nt < 4; nt++) {
                int col = warp_n * 32 + nt * 8 + 2 * lt;
                *(__half2*)(hwh + r * 64 + col) =
                    __floats2half2_rn(c[mt][nt][half * 2 + 0], c[mt][nt][half * 2 + 1]);
            }
        }
    }
}

// ---------------- merged K+V projection GEMM (fp16 A in, fp16 scatter out) ----------------
__global__ void __launch_bounds__(512, 1)
gemm_kv_k(const __half* __restrict__ A, const float* __restrict__ Wsrc,
          const float* __restrict__ abias, const float* __restrict__ ebias,
          const int* __restrict__ gidx, __half* __restrict__ gK, __half* __restrict__ gV) {
    constexpr int K = 64, BM = 128, BK = 32, NT = 2;
    constexpr int WPAD = K + 4;
    constexpr int APAD = BK + 4;

    extern __shared__ float sm[];
    float* Wsh = sm;
    float* Ash = sm + 128 * WPAD;

    const int tid = threadIdx.x;
    const int wid = tid >> 5, lane = tid & 31;
    const int warp_m = wid & 3, warp_n = wid >> 2;
    const int lg = lane >> 2, lt = lane & 3;
    const long long row0 = (long long)blockIdx.x * BM;

    for (int i = tid * 4; i < 128 * K; i += 512 * 4) {
        int n = i / K, k = i % K;
        float4 w = *(const float4*)(Wsrc + n * K + k);
        *(float4*)(Wsh + n * WPAD + k) = w;
    }

    float4 areg[2];
    auto lda = [&](int kt) {
#pragma unroll
        for (int it = 0; it < 2; it++) {
            int idx = it * 512 + tid;
            int r = idx >> 3, kq = idx & 7;
            long long grow = row0 + r;
            float4 v = make_float4(0.f, 0.f, 0.f, 0.f);
            if (grow < MTOT)
                v = load_h4_relu(A + grow * K + kt * BK + kq * 4, abias, kt * BK + kq * 4);
            areg[it] = v;
        }
    };
    auto sts = [&](int buf) {
        float* dst = Ash + buf * BM * APAD;
#pragma unroll
        for (int it = 0; it < 2; it++) {
            int idx = it * 512 + tid;
            int r = idx >> 3, kq = idx & 7;
            *(float4*)(dst + r * APAD + kq * 4) = areg[it];
        }
    };

    float c[2][4][4];
#pragma unroll
    for (int mt = 0; mt < 2; mt++)
#pragma unroll
        for (int nt = 0; nt < 4; nt++)
#pragma unroll
            for (int i = 0; i < 4; i++) c[mt][nt][i] = 0.f;

    lda(0);
    sts(0);

    for (int kt = 0; kt < NT; kt++) {
        __syncthreads();
        if (kt + 1 < NT) lda(kt + 1);
        const float* As = Ash + (kt & 1) * BM * APAD;
#pragma unroll
        for (int ks = 0; ks < 4; ks++) {
            const int k0 = ks * 8 + lt;
            unsigned ahi[2][4], alo[2][4];
#pragma unroll
            for (int mt = 0; mt < 2; mt++) {
                int ar = warp_m * 32 + mt * 16 + lg;
                float f0 = As[ar * APAD + k0];
                float f1 = As[(ar + 8) * APAD + k0];
                float f2 = As[ar * APAD + k0 + 4];
                float f3 = As[(ar + 8) * APAD + k0 + 4];
                split_tf32(f0, ahi[mt][0], alo[mt][0]);
                split_tf32(f1, ahi[mt][1], alo[mt][1]);
                split_tf32(f2, ahi[mt][2], alo[mt][2]);
                split_tf32(f3, ahi[mt][3], alo[mt][3]);
            }
            unsigned bhi[4][2], blo[4][2];
#pragma unroll
            for (int nt = 0; nt < 4; nt++) {
                int bn = warp_n * 32 + nt * 8 + lg;
                float g0 = Wsh[bn * WPAD + kt * BK + k0];
                float g1 = Wsh[bn * WPAD + kt * BK + k0 + 4];
                split_tf32(g0, bhi[nt][0], blo[nt][0]);
                split_tf32(g1, bhi[nt][1], blo[nt][1]);
            }
#pragma unroll
            for (int mt = 0; mt < 2; mt++)
#pragma unroll
                for (int nt = 0; nt < 4; nt++) {
                    mma_tf32(c[mt][nt], ahi[mt][0], ahi[mt][1], ahi[mt][2], ahi[mt][3],
                             bhi[nt][0], bhi[nt][1]);
                    mma_tf32(c[mt][nt], alo[mt][0], alo[mt][1], alo[mt][2], alo[mt][3],
                             bhi[nt][0], bhi[nt][1]);
                    mma_tf32(c[mt][nt], ahi[mt][0], ahi[mt][1], ahi[mt][2], ahi[mt][3],
                             blo[nt][0], blo[nt][1]);
                }
        }
        if (kt + 1 < NT) sts((kt + 1) & 1);
    }

#pragma unroll
    for (int mt = 0; mt < 2; mt++) {
        long long r_lo = row0 + warp_m * 32 + mt * 16 + lg;
#pragma unroll
        for (int half = 0; half < 2; half++) {
            long long r = r_lo + half * 8;
            if (r >= MTOT) continue;
            unsigned rr = (unsigned)r;
            unsigned t = rr / (unsigned)N_;
            unsigned n = rr - t * (unsigned)N_;
            int ridx = __ldg(gidx + (size_t)t * R_ + n);
            size_t rowoff = ((size_t)ridx * T_ + t) * 64;
#pragma unroll
            for (int nt = 0; nt < 4; nt++) {
                int col = warp_n * 32 + nt * 8 + 2 * lt;
                float2 b = *(const float2*)(ebias + col);
                __half* base = (col < 64 ? gK + rowoff + col : gV + rowoff + (col - 64));
                *(__half2*)base = __floats2half2_rn(c[mt][nt][half * 2 + 0] + b.x,
                                                    c[mt][nt][half * 2 + 1] + b.y);
            }
        }
    }
}

// ---------------- te9: relu(h2[t=9] + b2) scattered by gidx (standalone) ----------------
__global__ void te9_k(const __half* __restrict__ h2, const float* __restrict__ b2,
                      const int* __restrict__ gidx, float* __restrict__ te9) {
    int idx = blockIdx.x * blockDim.x + threadIdx.x;
    if (idx >= N_ * D_) return;
    int n = idx >> 6, c = idx & 63;
    float v = fmaxf(__half2float(h2[((size_t)9 * N_ + n) * 64 + c]) + b2[c], 0.f);
    te9[(size_t)__ldg(gidx + (size_t)9 * R_ + n) * 64 + c] = v;
}

// ---------------- tail ----------------
#define TAIL_WARPS 8
#define TAIL_SMEM  ((12288 + 704 + TAIL_WARPS * 1456) * 4)

__device__ __forceinline__ float warp_sum(float v) {
#pragma unroll
    for (int off = 16; off; off >>= 1) v += __shfl_xor_sync(0xffffffffu, v, off);
    return v;
}

__global__ void tail_k(const float* __restrict__ inW, const float* __restrict__ inB,
                       const float* __restrict__ outW, const float* __restrict__ outB,
                       const float* __restrict__ w1, const float* __restrict__ w2,
                       const float* __restrict__ w3, const float* __restrict__ w4,
                       const float* __restrict__ ln1g, const float* __restrict__ ln1b,
                       const float* __restrict__ ln2g, const float* __restrict__ ln2b,
                       const float* __restrict__ fcW, const float* __restrict__ fcB,
                       const float* __restrict__ te9, const __half* __restrict__ gK,
                       const __half* __restrict__ gV, float* __restrict__ out) {
    extern __shared__ float sh[];
    float* Wq = sh;
    float* Wo = sh + 4096;
    float* Wf = sh + 8192;
    float* cv = sh + 12288;

    int tid = threadIdx.x;
    for (int i = tid; i < 4096; i += TAIL_WARPS * 32) {
        int k = i >> 6, j = i & 63;
        Wq[i] = inW[j * 64 + k];
        Wo[i] = outW[j * 64 + k];
        Wf[i] = fcW[j * 64 + k];
    }
    if (tid < 64) {
        cv[tid]       = inB[tid];
        cv[64 + tid]  = outB[tid];
        cv[128 + tid] = fcB[tid];
        cv[192 + tid] = w1[(T_ - 1) * 64 + tid];
        cv[256 + tid] = w2[(T_ - 1) * 64 + tid];
        cv[320 + tid] = ln1g[tid];
        cv[384 + tid] = ln1b[tid];
        cv[448 + tid] = w3[tid];
        cv[512 + tid] = w4[tid];
        cv[576 + tid] = ln2g[tid];
        cv[640 + tid] = ln2b[tid];
    }
    __syncthreads();

    int warp = tid >> 5, lane = tid & 31;
    float* wb   = cv + 704 + warp * 1456;
    float* pvec = wb;
    float* pq   = wb + 64;
    float* kb   = wb + 128;
    float* vb   = wb + 768;
    float* sc   = wb + 1408;

    int gw = blockIdx.x * TAIL_WARPS + warp;
    int nw = gridDim.x * TAIL_WARPS;

    for (int r = gw; r < R_; r += nw) {
        pvec[lane]      = te9[(size_t)r * 64 + lane];
        pvec[lane + 32] = te9[(size_t)r * 64 + lane + 32];
        const __half2* kr = (const __half2*)(gK + (size_t)r * 640);
        const __half2* vr = (const __half2*)(gV + (size_t)r * 640);
        for (int i = lane; i < 320; i += 32) {
            *(float2*)(kb + 2 * i) = __half22float2(__ldg(kr + i));
            *(float2*)(vb + 2 * i) = __half22float2(__ldg(vr + i));
        }
        __syncwarp();

        float q0 = cv[lane], q1 = cv[lane + 32];
        for (int k = 0; k < 64; k++) {
            float xv = pvec[k];
            q0 = fmaf(xv, Wq[k * 64 + lane], q0);
            q1 = fmaf(xv, Wq[k * 64 + lane + 32], q1);
        }
        pq[lane] = q0; pq[lane + 32] = q1;
        __syncwarp();

        for (int p = lane; p < H_ * T_; p += 32) {
            int h = p / T_, tt = p - h * T_;
            const float* qh = pq + h * 16;
            const float* kh = kb + tt * 64 + h * 16;
            float s = 0.f;
#pragma unroll
            for (int d = 0; d < 16; d++) s = fmaf(qh[d], kh[d], s);
            sc[p] = s * 0.25f;
        }
        __syncwarp();

        if (lane < H_) {
            float mx = -1e30f;
#pragma unroll
            for (int tt = 0; tt < T_; tt++) mx = fmaxf(mx, sc[lane * T_ + tt]);
            float sm = 0.f;
#pragma unroll
            for (int tt = 0; tt < T_; tt++) {
                float ev = __expf(sc[lane * T_ + tt] - mx);
                sc[lane * T_ + tt] = ev; sm += ev;
            }
            float inv = 1.f / sm;
#pragma unroll
            for (int tt = 0; tt < T_; tt++) sc[lane * T_ + tt] *= inv;
        }
        __syncwarp();

        int h0 = lane >> 4, h1 = (lane + 32) >> 4;
        float a0 = 0.f, a1 = 0.f;
#pragma unroll
        for (int tt = 0; tt < T_; tt++) {
            a0 = fmaf(sc[h0 * T_ + tt], vb[tt * 64 + lane], a0);
            a1 = fmaf(sc[h1 * T_ + tt], vb[tt * 64 + lane + 32], a1);
        }
        pq[lane] = a0; pq[lane + 32] = a1;
        __syncwarp();

        float o0 = cv[64 + lane], o1 = cv[64 + lane + 32];
        for (int k = 0; k < 64; k++) {
            float xv = pq[k];
            o0 = fmaf(xv, Wo[k * 64 + lane], o0);
            o1 = fmaf(xv, Wo[k * 64 + lane + 32], o1);
        }

        float y0 = cv[192 + lane] * pvec[lane] + cv[256 + lane] * o0;
        float y1 = cv[192 + lane + 32] * pvec[lane + 32] + cv[256 + lane + 32] * o1;
        float mu = warp_sum(y0 + y1) * (1.f / 64.f);
        float d0 = y0 - mu, d1 = y1 - mu;
        float var = warp_sum(d0 * d0 + d1 * d1) * (1.f / 64.f);
        float rs = rsqrtf(var + 1e-5f);
        float f0 = d0 * rs * cv[320 + lane] + cv[384 + lane];
        float f1 = d1 * rs * cv[320 + lane + 32] + cv[384 + lane + 32];
        __syncwarp();
        pvec[lane] = f0; pvec[lane + 32] = f1;
        __syncwarp();

        float u0 = cv[128 + lane], u1 = cv[128 + lane + 32];
        for (int k = 0; k < 64; k++) {
            float xv = pvec[k];
            u0 = fmaf(xv, Wf[k * 64 + lane], u0);
            u1 = fmaf(xv, Wf[k * 64 + lane + 32], u1);
        }
        float z0 = cv[448 + lane] * f0 + cv[512 + lane] * u0;
        float z1 = cv[448 + lane + 32] * f1 + cv[512 + lane + 32] * u1;
        float mu2 = warp_sum(z0 + z1) * (1.f / 64.f);
        float e0 = z0 - mu2, e1 = z1 - mu2;
        float var2 = warp_sum(e0 * e0 + e1 * e1) * (1.f / 64.f);
        float rs2 = rsqrtf(var2 + 1e-5f);
        out[(size_t)r * 64 + lane]      = e0 * rs2 * cv[576 + lane] + cv[640 + lane];
        out[(size_t)r * 64 + lane + 32] = e1 * rs2 * cv[576 + lane + 32] + cv[640 + lane + 32];
        __syncwarp();
    }
}

// ---------------- launch ----------------
extern "C" void kernel_launch(void* const* d_in, const int* in_sizes, int n_in,
                              void* d_out, int out_size) {
    const float* x          = (const float*)d_in[0];
    const int*   edge_index = (const int*)  d_in[1];
    const float* edge_weight= (const float*)d_in[2];
    const int*   global_idx = (const int*)  d_in[3];
    const float* gcn1_w     = (const float*)d_in[4];
    const float* gcn1_b     = (const float*)d_in[5];
    const float* gcn2_w     = (const float*)d_in[6];
    const float* gcn2_b     = (const float*)d_in[7];
    const float* in_proj_w  = (const float*)d_in[8];
    const float* in_proj_b  = (const float*)d_in[9];
    const float* out_proj_w = (const float*)d_in[10];
    const float* out_proj_b = (const float*)d_in[11];
    const float* w1         = (const float*)d_in[12];
    const float* w2         = (const float*)d_in[13];
    const float* w3         = (const float*)d_in[14];
    const float* w4         = (const float*)d_in[15];
    const float* ln1_g      = (const float*)d_in[16];
    const float* ln1_b      = (const float*)d_in[17];
    const float* ln2_g      = (const float*)d_in[18];
    const float* ln2_b      = (const float*)d_in[19];
    const float* fc_w       = (const float*)d_in[20];
    const float* fc_b       = (const float*)d_in[21];
    float* out = (float*)d_out;

    float *deg, *te9;
    float2* degcnt;
    __half *hwh, *h1, *h2, *gk, *gv;
    int *offs, *offw, *bsum;
    unsigned* bucket;
    cudaGetSymbolAddress((void**)&degcnt, g_degcnt);
    cudaGetSymbolAddress((void**)&deg,  g_deg);
    cudaGetSymbolAddress((void**)&offs, g_offs);
    cudaGetSymbolAddress((void**)&offw, g_offw);
    cudaGetSymbolAddress((void**)&bsum, g_bsum);
    cudaGetSymbolAddress((void**)&bucket, g_bucket);
    cudaGetSymbolAddress((void**)&hwh, g_hwh);
    cudaGetSymbolAddress((void**)&h1,  g_h1);
    cudaGetSymbolAddress((void**)&h2,  g_h2);
    cudaGetSymbolAddress((void**)&gk,  g_k);
    cudaGetSymbolAddress((void**)&gv,  g_v);
    cudaGetSymbolAddress((void**)&te9, g_te9);

    const int SM_G1 = (64 * (128 + 4) + 4 * 128 * 36) * 4;   // 107520
    const int SM_G2 = (64 * (64 + 4)  + 2 * 128 * 36) * 4;   // 54272
    const int SM_KV = (128 * (64 + 4) + 2 * 128 * 36) * 4;   // 71680
    cudaFuncSetAttribute((const void*)gemm1_ca_k,
                         cudaFuncAttributeMaxDynamicSharedMemorySize, SM_G1);
    cudaFuncSetAttribute((const void*)gemm2_k,
                         cudaFuncAttributeMaxDynamicSharedMemorySize, SM_G2);
    cudaFuncSetAttribute((const void*)gemm_kv_k,
                         cudaFuncAttributeMaxDynamicSharedMemorySize, SM_KV);
    cudaFuncSetAttribute(tail_k, cudaFuncAttributeMaxDynamicSharedMemorySize, TAIL_SMEM);

    const int NB_M  = (MTOT + 255) / 256;
    const int NB_G  = (MTOT + 127) / 128;   // 3907
    const dim3 GB_E((E_ + 255) / 256, T_);
    const int NB_AG = (MTOT * 8 + 255) / 256;

    // CSR build
    init_k  <<<NB_M, 256>>>(degcnt);
    pass1_k <<<GB_E, 256>>>(degcnt, edge_index, edge_weight);
    scan1_k <<<NSCAN, 256>>>(degcnt, offs, bsum);
    scan2_k <<<1, 128>>>(bsum, NSCAN);
    scan3_k <<<NB_M, 256>>>(offs, offw, bsum, degcnt, deg);
    scatter_k<<<GB_E, 256>>>(edge_index, edge_weight, deg, offw, bucket);

    // layer 1
    gemm1_ca_k<<<NB_G, 256, SM_G1>>>(x, gcn1_w, hwh);
    agg2_k<<<NB_AG, 256>>>(bucket, offs, offw, deg, hwh, h1);

    // layer 2
    gemm2_k<<<NB_G, 256, SM_G2>>>(h1, gcn2_w, gcn1_b, hwh);
    agg2_k<<<NB_AG, 256>>>(bucket, offs, offw, deg, hwh, h2);

    // merged K+V projection
    gemm_kv_k<<<NB_G, 512, SM_KV>>>(h2, in_proj_w + 64 * 64, gcn2_b,
                                    in_proj_b + 64, global_idx, gk, gv);
    te9_k<<<(N_ * D_ + 255) / 256, 256>>>(h2, gcn2_b, global_idx, te9);

    tail_k<<<296, TAIL_WARPS * 32, TAIL_SMEM>>>(in_proj_w, in_proj_b, out_proj_w, out_proj_b,
                                                w1, w2, w3, w4, ln1_g, ln1_b, ln2_g, ln2_b,
                                                fc_w, fc_b, te9, gk, gv, out);
}

// round 16
// speedup vs baseline: 1.0900x; 1.0011x over previous
#include <cuda_runtime.h>
#include <cuda_fp16.h>
#include <cstdint>

#define T_   10
#define N_   50000
#define R_   50000
#define DIN_ 128
#define D_   64
#define H_   4
#define E_   400000
#define MTOT (T_ * N_)   // 500000
#define SCAN_BLK 4096
#define NSCAN ((MTOT + SCAN_BLK - 1) / SCAN_BLK)   // 123

// ---------------- scratch ----------------
__device__ float2   g_degcnt[(size_t)MTOT];
__device__ float    g_deg[(size_t)MTOT];
__device__ int      g_offs[(size_t)MTOT];
__device__ int      g_offw[(size_t)MTOT];
__device__ int      g_bsum[256];
__device__ unsigned g_bucket[(size_t)T_ * E_];   // packed: src(16) | half(c)(16)
__device__ __half   g_hwh[(size_t)MTOT * D_];
__device__ __half   g_h1 [(size_t)MTOT * D_];
__device__ __half   g_h2 [(size_t)MTOT * D_];
__device__ __half   g_k  [(size_t)R_ * T_ * D_];
__device__ __half   g_v  [(size_t)R_ * T_ * D_];
__device__ float    g_te9[(size_t)R_ * D_];

// ---------------- init / degree+count (fused vector RED) ----------------
__global__ void init_k(float2* degcnt) {
    int i = blockIdx.x * blockDim.x + threadIdx.x;
    if (i < MTOT) degcnt[i] = make_float2(1.0f, 0.0f);
}
__global__ void pass1_k(float2* degcnt, const int* __restrict__ edge_index,
                        const float* __restrict__ ew) {
    int t = blockIdx.y;
    int e = blockIdx.x * blockDim.x + threadIdx.x;
    if (e < E_) {
        int d = __ldg(edge_index + (size_t)t * 2 * E_ + E_ + e);
        float w = __ldg(ew + (size_t)t * E_ + e);
        float* p = (float*)&degcnt[t * N_ + d];
        asm volatile("red.global.add.v2.f32 [%0], {%1,%2};"
                     :: "l"(p), "f"(w), "f"(1.0f) : "memory");
    }
}

// ---------------- scan ----------------
__global__ void scan1_k(const float2* __restrict__ degcnt, int* __restrict__ offs,
                        int* __restrict__ bsum) {
    __shared__ int ts[256];
    int b = blockIdx.x, tid = threadIdx.x;
    int base = b * SCAN_BLK + tid * 16;
    int v[16]; int s = 0;
#pragma unroll
    for (int i = 0; i < 16; i++) {
        int idx = base + i;
        v[i] = (idx < MTOT) ? (int)__ldg(&degcnt[idx].y) : 0;
        s += v[i];
    }
    ts[tid] = s;
    __syncthreads();
    for (int off = 1; off < 256; off <<= 1) {
        int x = (tid >= off) ? ts[tid - off] : 0;
        __syncthreads();
        ts[tid] += x;
        __syncthreads();
    }
    int excl = ts[tid] - s;
    if (tid == 255) bsum[b] = ts[255];
    int run = excl;
#pragma unroll
    for (int i = 0; i < 16; i++) {
        int idx = base + i;
        if (idx < MTOT) offs[idx] = run;
        run += v[i];
    }
}
__global__ void scan2_k(int* bsum, int nb) {
    __shared__ int s[128];
    int tid = threadIdx.x;
    int v = (tid < nb) ? bsum[tid] : 0;
    s[tid] = v;
    __syncthreads();
    for (int off = 1; off < 128; off <<= 1) {
        int x = (tid >= off) ? s[tid - off] : 0;
        __syncthreads();
        s[tid] += x;
        __syncthreads();
    }
    if (tid < nb) bsum[tid] = s[tid] - v;
}
__global__ void scan3_k(int* __restrict__ offs, int* __restrict__ offw,
                        const int* __restrict__ bsum, const float2* __restrict__ degcnt,
                        float* __restrict__ dinv) {
    int i = blockIdx.x * blockDim.x + threadIdx.x;
    if (i < MTOT) {
        int v = offs[i] + bsum[i >> 12];
        offs[i] = v;
        offw[i] = v;
        dinv[i] = rsqrtf(__ldg(&degcnt[i].x));
    }
}

// ---------------- scatter edges into packed CSR buckets ----------------
__global__ void scatter_k(const int* __restrict__ edge_index, const float* __restrict__ ew,
                          const float* __restrict__ dinv, int* __restrict__ offw,
                          unsigned* __restrict__ bucket) {
    int t = blockIdx.y;
    int e = blockIdx.x * blockDim.x + threadIdx.x;
    if (e >= E_) return;
    const int* src = edge_index + (size_t)t * 2 * E_;
    int s = __ldg(src + e), d = __ldg(src + E_ + e);
    float w = __ldg(ew + (size_t)t * E_ + e);
    float c = __ldg(dinv + t * N_ + s) * w * __ldg(dinv + t * N_ + d);
    int pos = atomicAdd(&offw[t * N_ + d], 1);
    unsigned ch = (unsigned)__half_as_ushort(__float2half_rn(c));
    bucket[pos] = (unsigned)s | (ch << 16);
}

// ---------------- gather aggregation (fp16 src, fp32 acc, fp16 out, 2x ILP) ----------------
__device__ __forceinline__ void acc_half8(float4& a0, float4& a1, float c, uint4 raw) {
    const __half2* h = (const __half2*)&raw;
    float2 f0 = __half22float2(h[0]);
    float2 f1 = __half22float2(h[1]);
    float2 f2 = __half22float2(h[2]);
    float2 f3 = __half22float2(h[3]);
    a0.x = fmaf(c, f0.x, a0.x); a0.y = fmaf(c, f0.y, a0.y);
    a0.z = fmaf(c, f1.x, a0.z); a0.w = fmaf(c, f1.y, a0.w);
    a1.x = fmaf(c, f2.x, a1.x); a1.y = fmaf(c, f2.y, a1.y);
    a1.z = fmaf(c, f3.x, a1.z); a1.w = fmaf(c, f3.y, a1.w);
}
__device__ __forceinline__ float bkt_c(unsigned b) {
    return __half2float(__ushort_as_half((unsigned short)(b >> 16)));
}

__global__ void agg2_k(const unsigned* __restrict__ bucket, const int* __restrict__ offs,
                       const int* __restrict__ offw, const float* __restrict__ dinv,
                       const __half* __restrict__ hwh, __half* __restrict__ out) {
    int idx = blockIdx.x * blockDim.x + threadIdx.x;
    int node = idx >> 3, sub = idx & 7;
    if (node >= MTOT) return;
    long long tb = (long long)(node / N_) * N_;
    float di = __ldg(dinv + node);
    float s2 = di * di;
    float4 acc0 = make_float4(0.f, 0.f, 0.f, 0.f);
    float4 acc1 = make_float4(0.f, 0.f, 0.f, 0.f);
    uint4 sv = __ldg((const uint4*)(hwh + (size_t)node * 64) + sub);
    acc_half8(acc0, acc1, s2, sv);
    int p = __ldg(offs + node), e = __ldg(offw + node);
    for (; p + 2 <= e; p += 2) {
        unsigned e0 = __ldg(bucket + p);
        unsigned e1 = __ldg(bucket + p + 1);
        uint4 g0 = __ldg((const uint4*)(hwh + (size_t)(tb + (e0 & 0xFFFFu)) * 64) + sub);
        uint4 g1 = __ldg((const uint4*)(hwh + (size_t)(tb + (e1 & 0xFFFFu)) * 64) + sub);
        acc_half8(acc0, acc1, bkt_c(e0), g0);
        acc_half8(acc0, acc1, bkt_c(e1), g1);
    }
    if (p < e) {
        unsigned ed = __ldg(bucket + p);
        uint4 gv = __ldg((const uint4*)(hwh + (size_t)(tb + (ed & 0xFFFFu)) * 64) + sub);
        acc_half8(acc0, acc1, bkt_c(ed), gv);
    }
    __half2 h0 = __floats2half2_rn(acc0.x, acc0.y);
    __half2 h1 = __floats2half2_rn(acc0.z, acc0.w);
    __half2 h2 = __floats2half2_rn(acc1.x, acc1.y);
    __half2 h3 = __floats2half2_rn(acc1.z, acc1.w);
    uint4 pk;
    pk.x = *(unsigned*)&h0; pk.y = *(unsigned*)&h1;
    pk.z = *(unsigned*)&h2; pk.w = *(unsigned*)&h3;
    ((uint4*)(out + (size_t)node * 64))[sub] = pk;
}

// ---------------- tf32 helpers ----------------
__device__ __forceinline__ void mma_tf32(float* c, unsigned a0, unsigned a1,
                                         unsigned a2, unsigned a3,
                                         unsigned b0, unsigned b1) {
    asm volatile(
        "mma.sync.aligned.m16n8k8.row.col.f32.tf32.tf32.f32 "
        "{%0,%1,%2,%3}, {%4,%5,%6,%7}, {%8,%9}, {%0,%1,%2,%3};"
        : "+f"(c[0]), "+f"(c[1]), "+f"(c[2]), "+f"(c[3])
        : "r"(a0), "r"(a1), "r"(a2), "r"(a3), "r"(b0), "r"(b1));
}
__device__ __forceinline__ void split_tf32(float f, unsigned& hi, unsigned& lo) {
    unsigned u = __float_as_uint(f) & 0xFFFFE000u;
    hi = u;
    lo = __float_as_uint(f - __uint_as_float(u));
}

__device__ __forceinline__ float4 load_h4_relu(const __half* p, const float* bias, int boff) {
    __half2 a = __ldg((const __half2*)p);
    __half2 b = __ldg((const __half2*)p + 1);
    float2 lo = __half22float2(a), hi = __half22float2(b);
    float4 bb = *(const float4*)(bias + boff);
    float4 v;
    v.x = fmaxf(lo.x + bb.x, 0.f);
    v.y = fmaxf(lo.y + bb.y, 0.f);
    v.z = fmaxf(hi.x + bb.z, 0.f);
    v.w = fmaxf(hi.y + bb.w, 0.f);
    return v;
}

// ---------------- layer-1 GEMM: cp.async 4-stage, fp32 in, fp16 out ----------------
__global__ void __launch_bounds__(256, 2)
gemm1_ca_k(const float* __restrict__ A, const float* __restrict__ Wsrc,
           __half* __restrict__ hwh) {
    constexpr int K = 128, BM = 128, BK = 32, NT = 4;
    constexpr int WPAD = K + 4;
    constexpr int APAD = BK + 4;

    extern __shared__ float sm[];
    float* Wsh = sm;
    float* Ash = sm + 64 * WPAD;

    const int tid = threadIdx.x;
    const int wid = tid >> 5, lane = tid & 31;
    const int warp_m = wid & 3, warp_n = wid >> 2;
    const int lg = lane >> 2, lt = lane & 3;
    const long long row0 = (long long)blockIdx.x * BM;

#pragma unroll
    for (int kt = 0; kt < NT; kt++) {
        float* dstbase = Ash + kt * BM * APAD;
#pragma unroll
        for (int it = 0; it < 4; it++) {
            int idx = it * 256 + tid;
            int r = idx >> 3, kq = idx & 7;
            long long grow = row0 + r;
            long long srow = (grow < MTOT) ? grow : 0;
            const float* src = A + srow * K + kt * BK + kq * 4;
            unsigned dst = (unsigned)__cvta_generic_to_shared(dstbase + r * APAD + kq * 4);
            int nbytes = (grow < MTOT) ? 16 : 0;
            asm volatile("cp.async.cg.shared.global [%0], [%1], 16, %2;"
                         :: "r"(dst), "l"(src), "r"(nbytes) : "memory");
        }
        asm volatile("cp.async.commit_group;" ::: "memory");
    }

    for (int i = tid * 4; i < 64 * K; i += 256 * 4) {
        int n = i / K, k = i % K;
        float4 w = *(const float4*)(Wsrc + n * K + k);
        *(float4*)(Wsh + n * WPAD + k) = w;
    }

    float c[2][4][4];
#pragma unroll
    for (int mt = 0; mt < 2; mt++)
#pragma unroll
        for (int nt = 0; nt < 4; nt++)
#pragma unroll
            for (int i = 0; i < 4; i++) c[mt][nt][i] = 0.f;

#pragma unroll
    for (int kt = 0; kt < NT; kt++) {
        if (kt == 0)      asm volatile("cp.async.wait_group 3;" ::: "memory");
        else if (kt == 1) asm volatile("cp.async.wait_group 2;" ::: "memory");
        else if (kt == 2) asm volatile("cp.async.wait_group 1;" ::: "memory");
        else              asm volatile("cp.async.wait_group 0;" ::: "memory");
        __syncthreads();
        const float* As = Ash + kt * BM * APAD;
#pragma unroll
        for (int ks = 0; ks < 4; ks++) {
            const int k0 = ks * 8 + lt;
            unsigned ahi[2][4], alo[2][4];
#pragma unroll
            for (int mt = 0; mt < 2; mt++) {
                int ar = warp_m * 32 + mt * 16 + lg;
                float f0 = As[ar * APAD + k0];
                float f1 = As[(ar + 8) * APAD + k0];
                float f2 = As[ar * APAD + k0 + 4];
                float f3 = As[(ar + 8) * APAD + k0 + 4];
                split_tf32(f0, ahi[mt][0], alo[mt][0]);
                split_tf32(f1, ahi[mt][1], alo[mt][1]);
                split_tf32(f2, ahi[mt][2], alo[mt][2]);
                split_tf32(f3, ahi[mt][3], alo[mt][3]);
            }
            unsigned bhi[4][2], blo[4][2];
#pragma unroll
            for (int nt = 0; nt < 4; nt++) {
                int bn = warp_n * 32 + nt * 8 + lg;
                float g0 = Wsh[bn * WPAD + kt * BK + k0];
                float g1 = Wsh[bn * WPAD + kt * BK + k0 + 4];
                split_tf32(g0, bhi[nt][0], blo[nt][0]);
                split_tf32(g1, bhi[nt][1], blo[nt][1]);
            }
#pragma unroll
            for (int mt = 0; mt < 2; mt++)
#pragma unroll
                for (int nt = 0; nt < 4; nt++) {
                    mma_tf32(c[mt][nt], ahi[mt][0], ahi[mt][1], ahi[mt][2], ahi[mt][3],
                             bhi[nt][0], bhi[nt][1]);
                    mma_tf32(c[mt][nt], alo[mt][0], alo[mt][1], alo[mt][2], alo[mt][3],
                             bhi[nt][0], bhi[nt][1]);
                    mma_tf32(c[mt][nt], ahi[mt][0], ahi[mt][1], ahi[mt][2], ahi[mt][3],
                             blo[nt][0], blo[nt][1]);
                }
        }
    }

#pragma unroll
    for (int mt = 0; mt < 2; mt++) {
        long long r_lo = row0 + warp_m * 32 + mt * 16 + lg;
#pragma unroll
        for (int half = 0; half < 2; half++) {
            long long r = r_lo + half * 8;
            if (r >= MTOT) continue;
#pragma unroll
            for (int nt = 0; nt < 4; nt++) {
                int col = warp_n * 32 + nt * 8 + 2 * lt;
                *(__half2*)(hwh + r * 64 + col) =
                    __floats2half2_rn(c[mt][nt][half * 2 + 0], c[mt][nt][half * 2 + 1]);
            }
        }
    }
}

// ---------------- layer-2 GEMM (K=64, fp16 A with relu(A+b) on load, fp16 out) ----------------
__global__ void __launch_bounds__(256, 2)
gemm2_k(const __half* __restrict__ A, const float* __restrict__ Wsrc,
        const float* __restrict__ abias, __half* __restrict__ hwh) {
    constexpr int K = 64, BM = 128, BK = 32, NT = 2;
    constexpr int WPAD = K + 4;
    constexpr int APAD = BK + 4;

    extern __shared__ float sm[];
    float* Wsh = sm;
    float* Ash = sm + 64 * WPAD;

    const int tid = threadIdx.x;
    const int wid = tid >> 5, lane = tid & 31;
    const int warp_m = wid & 3, warp_n = wid >> 2;
    const int lg = lane >> 2, lt = lane & 3;
    const long long row0 = (long long)blockIdx.x * BM;

    for (int i = tid * 4; i < 64 * K; i += 256 * 4) {
        int n = i / K, k = i % K;
        float4 w = *(const float4*)(Wsrc + n * K + k);
        *(float4*)(Wsh + n * WPAD + k) = w;
    }

    float4 areg[4];
    auto lda = [&](int kt) {
#pragma unroll
        for (int it = 0; it < 4; it++) {
            int idx = it * 256 + tid;
            int r = idx >> 3, kq = idx & 7;
            long long grow = row0 + r;
            float4 v = make_float4(0.f, 0.f, 0.f, 0.f);
            if (grow < MTOT)
                v = load_h4_relu(A + grow * K + kt * BK + kq * 4, abias, kt * BK + kq * 4);
            areg[it] = v;
        }
    };
    auto sts = [&](int buf) {
        float* dst = Ash + buf * BM * APAD;
#pragma unroll
        for (int it = 0; it < 4; it++) {
            int idx = it * 256 + tid;
            int r = idx >> 3, kq = idx & 7;
            *(float4*)(dst + r * APAD + kq * 4) = areg[it];
        }
    };

    float c[2][4][4];
#pragma unroll
    for (int mt = 0; mt < 2; mt++)
#pragma unroll
        for (int nt = 0; nt < 4; nt++)
#pragma unroll
            for (int i = 0; i < 4; i++) c[mt][nt][i] = 0.f;

    lda(0);
    sts(0);

    for (int kt = 0; kt < NT; kt++) {
        __syncthreads();
        if (kt + 1 < NT) lda(kt + 1);
        const float* As = Ash + (kt & 1) * BM * APAD;
#pragma unroll
        for (int ks = 0; ks < 4; ks++) {
            const int k0 = ks * 8 + lt;
            unsigned ahi[2][4], alo[2][4];
#pragma unroll
            for (int mt = 0; mt < 2; mt++) {
                int ar = warp_m * 32 + mt * 16 + lg;
                float f0 = As[ar * APAD + k0];
                float f1 = As[(ar + 8) * APAD + k0];
                float f2 = As[ar * APAD + k0 + 4];
                float f3 = As[(ar + 8) * APAD + k0 + 4];
                split_tf32(f0, ahi[mt][0], alo[mt][0]);
                split_tf32(f1, ahi[mt][1], alo[mt][1]);
                split_tf32(f2, ahi[mt][2], alo[mt][2]);
                split_tf32(f3, ahi[mt][3], alo[mt][3]);
            }
            unsigned bhi[4][2], blo[4][2];
#pragma unroll
            for (int nt = 0; nt < 4; nt++) {
                int bn = warp_n * 32 + nt * 8 + lg;
                float g0 = Wsh[bn * WPAD + kt * BK + k0];
                float g1 = Wsh[bn * WPAD + kt * BK + k0 + 4];
                split_tf32(g0, bhi[nt][0], blo[nt][0]);
                split_tf32(g1, bhi[nt][1], blo[nt][1]);
            }
#pragma unroll
            for (int mt = 0; mt < 2; mt++)
#pragma unroll
                for (int nt = 0; nt < 4; nt++) {
                    mma_tf32(c[mt][nt], ahi[mt][0], ahi[mt][1], ahi[mt][2], ahi[mt][3],
                             bhi[nt][0], bhi[nt][1]);
                    mma_tf32(c[mt][nt], alo[mt][0], alo[mt][1], alo[mt][2], alo[mt][3],
                             bhi[nt][0], bhi[nt][1]);
                    mma_tf32(c[mt][nt], ahi[mt][0], ahi[mt][1], ahi[mt][2], ahi[mt][3],
                             blo[nt][0], blo[nt][1]);
                }
        }
        if (kt + 1 < NT) sts((kt + 1) & 1);
    }

#pragma unroll
    for (int mt = 0; mt < 2; mt++) {
        long long r_lo = row0 + warp_m * 32 + mt * 16 + lg;
#pragma unroll
        for (int half = 0; half < 2; half++) {
            long long r = r_lo + half * 8;
            if (r >= MTOT) continue;
#pragma unroll
            for (int nt = 0; nt < 4; nt++) {
                int col = warp_n * 32 + nt * 8 + 2 * lt;
                *(__half2*)(hwh + r * 64 + col) =
                    __floats2half2_rn(c[mt][nt][half * 2 + 0], c[mt][nt][half * 2 + 1]);
            }
        }
    }
}

// ---------------- merged K+V projection GEMM (fp16 A in, fp16 scatter out) ----------------
__global__ void __launch_bounds__(512, 1)
gemm_kv_k(const __half* __restrict__ A, const float* __restrict__ Wsrc,
          const float* __restrict__ abias, const float* __restrict__ ebias,
          const int* __restrict__ gidx, __half* __restrict__ gK, __half* __restrict__ gV) {
    constexpr int K = 64, BM = 128, BK = 32, NT = 2;
    constexpr int WPAD = K + 4;
    constexpr int APAD = BK + 4;

    extern __shared__ float sm[];
    float* Wsh = sm;
    float* Ash = sm + 128 * WPAD;

    const int tid = threadIdx.x;
    const int wid = tid >> 5, lane = tid & 31;
    const int warp_m = wid & 3, warp_n = wid >> 2;
    const int lg = lane >> 2, lt = lane & 3;
    const long long row0 = (long long)blockIdx.x * BM;

    for (int i = tid * 4; i < 128 * K; i += 512 * 4) {
        int n = i / K, k = i % K;
        float4 w = *(const float4*)(Wsrc + n * K + k);
        *(float4*)(Wsh + n * WPAD + k) = w;
    }

    float4 areg[2];
    auto lda = [&](int kt) {
#pragma unroll
        for (int it = 0; it < 2; it++) {
            int idx = it * 512 + tid;
            int r = idx >> 3, kq = idx & 7;
            long long grow = row0 + r;
            float4 v = make_float4(0.f, 0.f, 0.f, 0.f);
            if (grow < MTOT)
                v = load_h4_relu(A + grow * K + kt * BK + kq * 4, abias, kt * BK + kq * 4);
            areg[it] = v;
        }
    };
    auto sts = [&](int buf) {
        float* dst = Ash + buf * BM * APAD;
#pragma unroll
        for (int it = 0; it < 2; it++) {
            int idx = it * 512 + tid;
            int r = idx >> 3, kq = idx & 7;
            *(float4*)(dst + r * APAD + kq * 4) = areg[it];
        }
    };

    float c[2][4][4];
#pragma unroll
    for (int mt = 0; mt < 2; mt++)
#pragma unroll
        for (int nt = 0; nt < 4; nt++)
#pragma unroll
            for (int i = 0; i < 4; i++) c[mt][nt][i] = 0.f;

    lda(0);
    sts(0);

    for (int kt = 0; kt < NT; kt++) {
        __syncthreads();
        if (kt + 1 < NT) lda(kt + 1);
        const float* As = Ash + (kt & 1) * BM * APAD;
#pragma unroll
        for (int ks = 0; ks < 4; ks++) {
            const int k0 = ks * 8 + lt;
            unsigned ahi[2][4], alo[2][4];
#pragma unroll
            for (int mt = 0; mt < 2; mt++) {
                int ar = warp_m * 32 + mt * 16 + lg;
                float f0 = As[ar * APAD + k0];
                float f1 = As[(ar + 8) * APAD + k0];
                float f2 = As[ar * APAD + k0 + 4];
                float f3 = As[(ar + 8) * APAD + k0 + 4];
                split_tf32(f0, ahi[mt][0], alo[mt][0]);
                split_tf32(f1, ahi[mt][1], alo[mt][1]);
                split_tf32(f2, ahi[mt][2], alo[mt][2]);
                split_tf32(f3, ahi[mt][3], alo[mt][3]);
            }
            unsigned bhi[4][2], blo[4][2];
#pragma unroll
            for (int nt = 0; nt < 4; nt++) {
                int bn = warp_n * 32 + nt * 8 + lg;
                float g0 = Wsh[bn * WPAD + kt * BK + k0];
                float g1 = Wsh[bn * WPAD + kt * BK + k0 + 4];
                split_tf32(g0, bhi[nt][0], blo[nt][0]);
                split_tf32(g1, bhi[nt][1], blo[nt][1]);
            }
#pragma unroll
            for (int mt = 0; mt < 2; mt++)
#pragma unroll
                for (int nt = 0; nt < 4; nt++) {
                    mma_tf32(c[mt][nt], ahi[mt][0], ahi[mt][1], ahi[mt][2], ahi[mt][3],
                             bhi[nt][0], bhi[nt][1]);
                    mma_tf32(c[mt][nt], alo[mt][0], alo[mt][1], alo[mt][2], alo[mt][3],
                             bhi[nt][0], bhi[nt][1]);
                    mma_tf32(c[mt][nt], ahi[mt][0], ahi[mt][1], ahi[mt][2], ahi[mt][3],
                             blo[nt][0], blo[nt][1]);
                }
        }
        if (kt + 1 < NT) sts((kt + 1) & 1);
    }

#pragma unroll
    for (int mt = 0; mt < 2; mt++) {
        long long r_lo = row0 + warp_m * 32 + mt * 16 + lg;
#pragma unroll
        for (int half = 0; half < 2; half++) {
            long long r = r_lo + half * 8;
            if (r >= MTOT) continue;
            unsigned rr = (unsigned)r;
            unsigned t = rr / (unsigned)N_;
            unsigned n = rr - t * (unsigned)N_;
            int ridx = __ldg(gidx + (size_t)t * R_ + n);
            size_t rowoff = ((size_t)ridx * T_ + t) * 64;
#pragma unroll
            for (int nt = 0; nt < 4; nt++) {
                int col = warp_n * 32 + nt * 8 + 2 * lt;
                float2 b = *(const float2*)(ebias + col);
                __half* base = (col < 64 ? gK + rowoff + col : gV + rowoff + (col - 64));
                *(__half2*)base = __floats2half2_rn(c[mt][nt][half * 2 + 0] + b.x,
                                                    c[mt][nt][half * 2 + 1] + b.y);
            }
        }
    }
}

// ---------------- te9: relu(h2[t=9] + b2) scattered by gidx (standalone) ----------------
__global__ void te9_k(const __half* __restrict__ h2, const float* __restrict__ b2,
                      const int* __restrict__ gidx, float* __restrict__ te9) {
    int idx = blockIdx.x * blockDim.x + threadIdx.x;
    if (idx >= N_ * D_) return;
    int n = idx >> 6, c = idx & 63;
    float v = fmaxf(__half2float(h2[((size_t)9 * N_ + n) * 64 + c]) + b2[c], 0.f);
    te9[(size_t)__ldg(gidx + (size_t)9 * R_ + n) * 64 + c] = v;
}

// ---------------- tail ----------------
#define TAIL_WARPS 8
#define TAIL_SMEM  ((12288 + 704 + TAIL_WARPS * 1456) * 4)

__device__ __forceinline__ float warp_sum(float v) {
#pragma unroll
    for (int off = 16; off; off >>= 1) v += __shfl_xor_sync(0xffffffffu, v, off);
    return v;
}

__global__ void tail_k(const float* __restrict__ inW, const float* __restrict__ inB,
                       const float* __restrict__ outW, const float* __restrict__ outB,
                       const float* __restrict__ w1, const float* __restrict__ w2,
                       const float* __restrict__ w3, const float* __restrict__ w4,
                       const float* __restrict__ ln1g, const float* __restrict__ ln1b,
                       const float* __restrict__ ln2g, const float* __restrict__ ln2b,
                       const float* __restrict__ fcW, const float* __restrict__ fcB,
                       const float* __restrict__ te9, const __half* __restrict__ gK,
                       const __half* __restrict__ gV, float* __restrict__ out) {
    extern __shared__ float sh[];
    float* Wq = sh;
    float* Wo = sh + 4096;
    float* Wf = sh + 8192;
    float* cv = sh + 12288;

    int tid = threadIdx.x;
    for (int i = tid; i < 4096; i += TAIL_WARPS * 32) {
        int k = i >> 6, j = i & 63;
        Wq[i] = inW[j * 64 + k];
        Wo[i] = outW[j * 64 + k];
        Wf[i] = fcW[j * 64 + k];
    }
    if (tid < 64) {
        cv[tid]       = inB[tid];
        cv[64 + tid]  = outB[tid];
        cv[128 + tid] = fcB[tid];
        cv[192 + tid] = w1[(T_ - 1) * 64 + tid];
        cv[256 + tid] = w2[(T_ - 1) * 64 + tid];
        cv[320 + tid] = ln1g[tid];
        cv[384 + tid] = ln1b[tid];
        cv[448 + tid] = w3[tid];
        cv[512 + tid] = w4[tid];
        cv[576 + tid] = ln2g[tid];
        cv[640 + tid] = ln2b[tid];
    }
    __syncthreads();

    int warp = tid >> 5, lane = tid & 31;
    float* wb   = cv + 704 + warp * 1456;
    float* pvec = wb;
    float* pq   = wb + 64;
    float* kb   = wb + 128;
    float* vb   = wb + 768;
    float* sc   = wb + 1408;

    int gw = blockIdx.x * TAIL_WARPS + warp;
    int nw = gridDim.x * TAIL_WARPS;

    for (int r = gw; r < R_; r += nw) {
        pvec[lane]      = te9[(size_t)r * 64 + lane];
        pvec[lane + 32] = te9[(size_t)r * 64 + lane + 32];
        const __half2* kr = (const __half2*)(gK + (size_t)r * 640);
        const __half2* vr = (const __half2*)(gV + (size_t)r * 640);
        for (int i = lane; i < 320; i += 32) {
            *(float2*)(kb + 2 * i) = __half22float2(__ldg(kr + i));
            *(float2*)(vb + 2 * i) = __half22float2(__ldg(vr + i));
        }
        __syncwarp();

        float q0 = cv[lane], q1 = cv[lane + 32];
        for (int k = 0; k < 64; k++) {
            float xv = pvec[k];
            q0 = fmaf(xv, Wq[k * 64 + lane], q0);
            q1 = fmaf(xv, Wq[k * 64 + lane + 32], q1);
        }
        pq[lane] = q0; pq[lane + 32] = q1;
        __syncwarp();

        for (int p = lane; p < H_ * T_; p += 32) {
            int h = p / T_, tt = p - h * T_;
            const float* qh = pq + h * 16;
            const float* kh = kb + tt * 64 + h * 16;
            float s = 0.f;
#pragma unroll
            for (int d = 0; d < 16; d++) s = fmaf(qh[d], kh[d], s);
            sc[p] = s * 0.25f;
        }
        __syncwarp();

        if (lane < H_) {
            float mx = -1e30f;
#pragma unroll
            for (int tt = 0; tt < T_; tt++) mx = fmaxf(mx, sc[lane * T_ + tt]);
            float sm = 0.f;
#pragma unroll
            for (int tt = 0; tt < T_; tt++) {
                float ev = __expf(sc[lane * T_ + tt] - mx);
                sc[lane * T_ + tt] = ev; sm += ev;
            }
            float inv = 1.f / sm;
#pragma unroll
            for (int tt = 0; tt < T_; tt++) sc[lane * T_ + tt] *= inv;
        }
        __syncwarp();

        int h0 = lane >> 4, h1 = (lane + 32) >> 4;
        float a0 = 0.f, a1 = 0.f;
#pragma unroll
        for (int tt = 0; tt < T_; tt++) {
            a0 = fmaf(sc[h0 * T_ + tt], vb[tt * 64 + lane], a0);
            a1 = fmaf(sc[h1 * T_ + tt], vb[tt * 64 + lane + 32], a1);
        }
        pq[lane] = a0; pq[lane + 32] = a1;
        __syncwarp();

        float o0 = cv[64 + lane], o1 = cv[64 + lane + 32];
        for (int k = 0; k < 64; k++) {
            float xv = pq[k];
            o0 = fmaf(xv, Wo[k * 64 + lane], o0);
            o1 = fmaf(xv, Wo[k * 64 + lane + 32], o1);
        }

        float y0 = cv[192 + lane] * pvec[lane] + cv[256 + lane] * o0;
        float y1 = cv[192 + lane + 32] * pvec[lane + 32] + cv[256 + lane + 32] * o1;
        float mu = warp_sum(y0 + y1) * (1.f / 64.f);
        float d0 = y0 - mu, d1 = y1 - mu;
        float var = warp_sum(d0 * d0 + d1 * d1) * (1.f / 64.f);
        float rs = rsqrtf(var + 1e-5f);
        float f0 = d0 * rs * cv[320 + lane] + cv[384 + lane];
        float f1 = d1 * rs * cv[320 + lane + 32] + cv[384 + lane + 32];
        __syncwarp();
        pvec[lane] = f0; pvec[lane + 32] = f1;
        __syncwarp();

        float u0 = cv[128 + lane], u1 = cv[128 + lane + 32];
        for (int k = 0; k < 64; k++) {
            float xv = pvec[k];
            u0 = fmaf(xv, Wf[k * 64 + lane], u0);
            u1 = fmaf(xv, Wf[k * 64 + lane + 32], u1);
        }
        float z0 = cv[448 + lane] * f0 + cv[512 + lane] * u0;
        float z1 = cv[448 + lane + 32] * f1 + cv[512 + lane + 32] * u1;
        float mu2 = warp_sum(z0 + z1) * (1.f / 64.f);
        float e0 = z0 - mu2, e1 = z1 - mu2;
        float var2 = warp_sum(e0 * e0 + e1 * e1) * (1.f / 64.f);
        float rs2 = rsqrtf(var2 + 1e-5f);
        out[(size_t)r * 64 + lane]      = e0 * rs2 * cv[576 + lane] + cv[640 + lane];
        out[(size_t)r * 64 + lane + 32] = e1 * rs2 * cv[576 + lane + 32] + cv[640 + lane + 32];
        __syncwarp();
    }
}

// ---------------- launch ----------------
extern "C" void kernel_launch(void* const* d_in, const int* in_sizes, int n_in,
                              void* d_out, int out_size) {
    const float* x          = (const float*)d_in[0];
    const int*   edge_index = (const int*)  d_in[1];
    const float* edge_weight= (const float*)d_in[2];
    const int*   global_idx = (const int*)  d_in[3];
    const float* gcn1_w     = (const float*)d_in[4];
    const float* gcn1_b     = (const float*)d_in[5];
    const float* gcn2_w     = (const float*)d_in[6];
    const float* gcn2_b     = (const float*)d_in[7];
    const float* in_proj_w  = (const float*)d_in[8];
    const float* in_proj_b  = (const float*)d_in[9];
    const float* out_proj_w = (const float*)d_in[10];
    const float* out_proj_b = (const float*)d_in[11];
    const float* w1         = (const float*)d_in[12];
    const float* w2         = (const float*)d_in[13];
    const float* w3         = (const float*)d_in[14];
    const float* w4         = (const float*)d_in[15];
    const float* ln1_g      = (const float*)d_in[16];
    const float* ln1_b      = (const float*)d_in[17];
    const float* ln2_g      = (const float*)d_in[18];
    const float* ln2_b      = (const float*)d_in[19];
    const float* fc_w       = (const float*)d_in[20];
    const float* fc_b       = (const float*)d_in[21];
    float* out = (float*)d_out;

    float *deg, *te9;
    float2* degcnt;
    __half *hwh, *h1, *h2, *gk, *gv;
    int *offs, *offw, *bsum;
    unsigned* bucket;
    cudaGetSymbolAddress((void**)&degcnt, g_degcnt);
    cudaGetSymbolAddress((void**)&deg,  g_deg);
    cudaGetSymbolAddress((void**)&offs, g_offs);
    cudaGetSymbolAddress((void**)&offw, g_offw);
    cudaGetSymbolAddress((void**)&bsum, g_bsum);
    cudaGetSymbolAddress((void**)&bucket, g_bucket);
    cudaGetSymbolAddress((void**)&hwh, g_hwh);
    cudaGetSymbolAddress((void**)&h1,  g_h1);
    cudaGetSymbolAddress((void**)&h2,  g_h2);
    cudaGetSymbolAddress((void**)&gk,  g_k);
    cudaGetSymbolAddress((void**)&gv,  g_v);
    cudaGetSymbolAddress((void**)&te9, g_te9);

    const int SM_G1 = (64 * (128 + 4) + 4 * 128 * 36) * 4;   // 107520
    const int SM_G2 = (64 * (64 + 4)  + 2 * 128 * 36) * 4;   // 54272
    const int SM_KV = (128 * (64 + 4) + 2 * 128 * 36) * 4;   // 71680
    cudaFuncSetAttribute((const void*)gemm1_ca_k,
                         cudaFuncAttributeMaxDynamicSharedMemorySize, SM_G1);
    cudaFuncSetAttribute((const void*)gemm2_k,
                         cudaFuncAttributeMaxDynamicSharedMemorySize, SM_G2);
    cudaFuncSetAttribute((const void*)gemm_kv_k,
                         cudaFuncAttributeMaxDynamicSharedMemorySize, SM_KV);
    cudaFuncSetAttribute(tail_k, cudaFuncAttributeMaxDynamicSharedMemorySize, TAIL_SMEM);

    const int NB_M  = (MTOT + 255) / 256;
    const int NB_G  = (MTOT + 127) / 128;   // 3907
    const dim3 GB_E((E_ + 255) / 256, T_);
    const int NB_AG = (MTOT * 8 + 255) / 256;

    // fork a side stream for the CSR build (overlaps with gemm1 on main stream)
    cudaStream_t s2;
    cudaStreamCreateWithFlags(&s2, cudaStreamNonBlocking);
    cudaEvent_t evFork, evJoin;
    cudaEventCreateWithFlags(&evFork, cudaEventDisableTiming);
    cudaEventCreateWithFlags(&evJoin, cudaEventDisableTiming);

    cudaEventRecord(evFork, 0);
    cudaStreamWaitEvent(s2, evFork, 0);

    // CSR build on side stream
    init_k  <<<NB_M, 256, 0, s2>>>(degcnt);
    pass1_k <<<GB_E, 256, 0, s2>>>(degcnt, edge_index, edge_weight);
    scan1_k <<<NSCAN, 256, 0, s2>>>(degcnt, offs, bsum);
    scan2_k <<<1, 128, 0, s2>>>(bsum, NSCAN);
    scan3_k <<<NB_M, 256, 0, s2>>>(offs, offw, bsum, degcnt, deg);
    scatter_k<<<GB_E, 256, 0, s2>>>(edge_index, edge_weight, deg, offw, bucket);
    cudaEventRecord(evJoin, s2);

    // layer-1 GEMM on main stream, concurrent with CSR build
    gemm1_ca_k<<<NB_G, 256, SM_G1>>>(x, gcn1_w, hwh);

    // join: agg2 needs both gemm1 output and the CSR structures
    cudaStreamWaitEvent(0, evJoin, 0);

    agg2_k<<<NB_AG, 256>>>(bucket, offs, offw, deg, hwh, h1);

    gemm2_k<<<NB_G, 256, SM_G2>>>(h1, gcn2_w, gcn1_b, hwh);
    agg2_k<<<NB_AG, 256>>>(bucket, offs, offw, deg, hwh, h2);

    gemm_kv_k<<<NB_G, 512, SM_KV>>>(h2, in_proj_w + 64 * 64, gcn2_b,
                                    in_proj_b + 64, global_idx, gk, gv);
    te9_k<<<(N_ * D_ + 255) / 256, 256>>>(h2, gcn2_b, global_idx, te9);

    tail_k<<<296, TAIL_WARPS * 32, TAIL_SMEM>>>(in_proj_w, in_proj_b, out_proj_w, out_proj_b,
                                                w1, w2, w3, w4, ln1_g, ln1_b, ln2_g, ln2_b,
                                                fc_w, fc_b, te9, gk, gv, out);
    // (stream/events intentionally not destroyed: destruction mid-capture is illegal;
    //  kernel_launch is invoked only a handful of times, host-side handles are tiny)
}

// round 17
// speedup vs baseline: 1.1066x; 1.0153x over previous
#include <cuda_runtime.h>
#include <cuda_fp16.h>
#include <cstdint>

#define T_   10
#define N_   50000
#define R_   50000
#define DIN_ 128
#define D_   64
#define H_   4
#define E_   400000
#define MTOT (T_ * N_)   // 500000
#define SCAN_BLK 4096
#define NSCAN ((MTOT + SCAN_BLK - 1) / SCAN_BLK)   // 123

// ---------------- scratch ----------------
__device__ float2   g_degcnt[(size_t)MTOT];
__device__ float    g_deg[(size_t)MTOT];
__device__ int      g_offs[(size_t)MTOT];
__device__ int      g_offw[(size_t)MTOT];
__device__ int      g_bsum[256];
__device__ unsigned g_bucket[(size_t)T_ * E_];   // packed: src(16) | half(c)(16)
__device__ __half   g_hwh[(size_t)MTOT * D_];
__device__ __half   g_h1 [(size_t)MTOT * D_];
__device__ __half   g_h2 [(size_t)MTOT * D_];
__device__ __half   g_k  [(size_t)R_ * T_ * D_];
__device__ __half   g_v  [(size_t)R_ * T_ * D_];
__device__ float    g_te9[(size_t)R_ * D_];

// ---------------- init / degree+count (fused vector RED) ----------------
__global__ void init_k(float2* degcnt) {
    int i = blockIdx.x * blockDim.x + threadIdx.x;
    if (i < MTOT) degcnt[i] = make_float2(1.0f, 0.0f);
}
__global__ void pass1_k(float2* degcnt, const int* __restrict__ edge_index,
                        const float* __restrict__ ew) {
    int t = blockIdx.y;
    int e = blockIdx.x * blockDim.x + threadIdx.x;
    if (e < E_) {
        int d = __ldg(edge_index + (size_t)t * 2 * E_ + E_ + e);
        float w = __ldg(ew + (size_t)t * E_ + e);
        float* p = (float*)&degcnt[t * N_ + d];
        asm volatile("red.global.add.v2.f32 [%0], {%1,%2};"
                     :: "l"(p), "f"(w), "f"(1.0f) : "memory");
    }
}

// ---------------- scan ----------------
__global__ void scan1_k(const float2* __restrict__ degcnt, int* __restrict__ offs,
                        int* __restrict__ bsum) {
    __shared__ int ts[256];
    int b = blockIdx.x, tid = threadIdx.x;
    int base = b * SCAN_BLK + tid * 16;
    int v[16]; int s = 0;
#pragma unroll
    for (int i = 0; i < 16; i++) {
        int idx = base + i;
        v[i] = (idx < MTOT) ? (int)__ldg(&degcnt[idx].y) : 0;
        s += v[i];
    }
    ts[tid] = s;
    __syncthreads();
    for (int off = 1; off < 256; off <<= 1) {
        int x = (tid >= off) ? ts[tid - off] : 0;
        __syncthreads();
        ts[tid] += x;
        __syncthreads();
    }
    int excl = ts[tid] - s;
    if (tid == 255) bsum[b] = ts[255];
    int run = excl;
#pragma unroll
    for (int i = 0; i < 16; i++) {
        int idx = base + i;
        if (idx < MTOT) offs[idx] = run;
        run += v[i];
    }
}
__global__ void scan2_k(int* bsum, int nb) {
    __shared__ int s[128];
    int tid = threadIdx.x;
    int v = (tid < nb) ? bsum[tid] : 0;
    s[tid] = v;
    __syncthreads();
    for (int off = 1; off < 128; off <<= 1) {
        int x = (tid >= off) ? s[tid - off] : 0;
        __syncthreads();
        s[tid] += x;
        __syncthreads();
    }
    if (tid < nb) bsum[tid] = s[tid] - v;
}
__global__ void scan3_k(int* __restrict__ offs, int* __restrict__ offw,
                        const int* __restrict__ bsum, const float2* __restrict__ degcnt,
                        float* __restrict__ dinv) {
    int i = blockIdx.x * blockDim.x + threadIdx.x;
    if (i < MTOT) {
        int v = offs[i] + bsum[i >> 12];
        offs[i] = v;
        offw[i] = v;
        dinv[i] = rsqrtf(__ldg(&degcnt[i].x));
    }
}

// ---------------- scatter edges into packed CSR buckets ----------------
__global__ void scatter_k(const int* __restrict__ edge_index, const float* __restrict__ ew,
                          const float* __restrict__ dinv, int* __restrict__ offw,
                          unsigned* __restrict__ bucket) {
    int t = blockIdx.y;
    int e = blockIdx.x * blockDim.x + threadIdx.x;
    if (e >= E_) return;
    const int* src = edge_index + (size_t)t * 2 * E_;
    int s = __ldg(src + e), d = __ldg(src + E_ + e);
    float w = __ldg(ew + (size_t)t * E_ + e);
    float c = __ldg(dinv + t * N_ + s) * w * __ldg(dinv + t * N_ + d);
    int pos = atomicAdd(&offw[t * N_ + d], 1);
    unsigned ch = (unsigned)__half_as_ushort(__float2half_rn(c));
    bucket[pos] = (unsigned)s | (ch << 16);
}

// ---------------- gather aggregation (fp16 src, fp32 acc, fp16 out, 2x ILP) ----------------
__device__ __forceinline__ void acc_half8(float4& a0, float4& a1, float c, uint4 raw) {
    const __half2* h = (const __half2*)&raw;
    float2 f0 = __half22float2(h[0]);
    float2 f1 = __half22float2(h[1]);
    float2 f2 = __half22float2(h[2]);
    float2 f3 = __half22float2(h[3]);
    a0.x = fmaf(c, f0.x, a0.x); a0.y = fmaf(c, f0.y, a0.y);
    a0.z = fmaf(c, f1.x, a0.z); a0.w = fmaf(c, f1.y, a0.w);
    a1.x = fmaf(c, f2.x, a1.x); a1.y = fmaf(c, f2.y, a1.y);
    a1.z = fmaf(c, f3.x, a1.z); a1.w = fmaf(c, f3.y, a1.w);
}
__device__ __forceinline__ float bkt_c(unsigned b) {
    return __half2float(__ushort_as_half((unsigned short)(b >> 16)));
}

__global__ void agg2_k(const unsigned* __restrict__ bucket, const int* __restrict__ offs,
                       const int* __restrict__ offw, const float* __restrict__ dinv,
                       const __half* __restrict__ hwh, __half* __restrict__ out) {
    int idx = blockIdx.x * blockDim.x + threadIdx.x;
    int node = idx >> 3, sub = idx & 7;
    if (node >= MTOT) return;
    long long tb = (long long)(node / N_) * N_;
    float di = __ldg(dinv + node);
    float s2 = di * di;
    float4 acc0 = make_float4(0.f, 0.f, 0.f, 0.f);
    float4 acc1 = make_float4(0.f, 0.f, 0.f, 0.f);
    uint4 sv = __ldg((const uint4*)(hwh + (size_t)node * 64) + sub);
    acc_half8(acc0, acc1, s2, sv);
    int p = __ldg(offs + node), e = __ldg(offw + node);
    for (; p + 2 <= e; p += 2) {
        unsigned e0 = __ldg(bucket + p);
        unsigned e1 = __ldg(bucket + p + 1);
        uint4 g0 = __ldg((const uint4*)(hwh + (size_t)(tb + (e0 & 0xFFFFu)) * 64) + sub);
        uint4 g1 = __ldg((const uint4*)(hwh + (size_t)(tb + (e1 & 0xFFFFu)) * 64) + sub);
        acc_half8(acc0, acc1, bkt_c(e0), g0);
        acc_half8(acc0, acc1, bkt_c(e1), g1);
    }
    if (p < e) {
        unsigned ed = __ldg(bucket + p);
        uint4 gv = __ldg((const uint4*)(hwh + (size_t)(tb + (ed & 0xFFFFu)) * 64) + sub);
        acc_half8(acc0, acc1, bkt_c(ed), gv);
    }
    __half2 h0 = __floats2half2_rn(acc0.x, acc0.y);
    __half2 h1 = __floats2half2_rn(acc0.z, acc0.w);
    __half2 h2 = __floats2half2_rn(acc1.x, acc1.y);
    __half2 h3 = __floats2half2_rn(acc1.z, acc1.w);
    uint4 pk;
    pk.x = *(unsigned*)&h0; pk.y = *(unsigned*)&h1;
    pk.z = *(unsigned*)&h2; pk.w = *(unsigned*)&h3;
    ((uint4*)(out + (size_t)node * 64))[sub] = pk;
}

// ---------------- tf32 helpers ----------------
__device__ __forceinline__ void mma_tf32(float* c, unsigned a0, unsigned a1,
                                         unsigned a2, unsigned a3,
                                         unsigned b0, unsigned b1) {
    asm volatile(
        "mma.sync.aligned.m16n8k8.row.col.f32.tf32.tf32.f32 "
        "{%0,%1,%2,%3}, {%4,%5,%6,%7}, {%8,%9}, {%0,%1,%2,%3};"
        : "+f"(c[0]), "+f"(c[1]), "+f"(c[2]), "+f"(c[3])
        : "r"(a0), "r"(a1), "r"(a2), "r"(a3), "r"(b0), "r"(b1));
}
__device__ __forceinline__ void split_tf32(float f, unsigned& hi, unsigned& lo) {
    unsigned u = __float_as_uint(f) & 0xFFFFE000u;
    hi = u;
    lo = __float_as_uint(f - __uint_as_float(u));
}

__device__ __forceinline__ float4 load_h4_relu(const __half* p, const float* bias, int boff) {
    __half2 a = __ldg((const __half2*)p);
    __half2 b = __ldg((const __half2*)p + 1);
    float2 lo = __half22float2(a), hi = __half22float2(b);
    float4 bb = *(const float4*)(bias + boff);
    float4 v;
    v.x = fmaxf(lo.x + bb.x, 0.f);
    v.y = fmaxf(lo.y + bb.y, 0.f);
    v.z = fmaxf(hi.x + bb.z, 0.f);
    v.w = fmaxf(hi.y + bb.w, 0.f);
    return v;
}

// ---------------- layer-1 GEMM: cp.async 4-stage, fp32 in, fp16 out ----------------
__global__ void __launch_bounds__(256, 2)
gemm1_ca_k(const float* __restrict__ A, const float* __restrict__ Wsrc,
           __half* __restrict__ hwh) {
    constexpr int K = 128, BM = 128, BK = 32, NT = 4;
    constexpr int WPAD = K + 4;
    constexpr int APAD = BK + 4;

    extern __shared__ float sm[];
    float* Wsh = sm;
    float* Ash = sm + 64 * WPAD;

    const int tid = threadIdx.x;
    const int wid = tid >> 5, lane = tid & 31;
    const int warp_m = wid & 3, warp_n = wid >> 2;
    const int lg = lane >> 2, lt = lane & 3;
    const long long row0 = (long long)blockIdx.x * BM;

#pragma unroll
    for (int kt = 0; kt < NT; kt++) {
        float* dstbase = Ash + kt * BM * APAD;
#pragma unroll
        for (int it = 0; it < 4; it++) {
            int idx = it * 256 + tid;
            int r = idx >> 3, kq = idx & 7;
            long long grow = row0 + r;
            long long srow = (grow < MTOT) ? grow : 0;
            const float* src = A + srow * K + kt * BK + kq * 4;
            unsigned dst = (unsigned)__cvta_generic_to_shared(dstbase + r * APAD + kq * 4);
            int nbytes = (grow < MTOT) ? 16 : 0;
            asm volatile("cp.async.cg.shared.global [%0], [%1], 16, %2;"
                         :: "r"(dst), "l"(src), "r"(nbytes) : "memory");
        }
        asm volatile("cp.async.commit_group;" ::: "memory");
    }

    for (int i = tid * 4; i < 64 * K; i += 256 * 4) {
        int n = i / K, k = i % K;
        float4 w = *(const float4*)(Wsrc + n * K + k);
        *(float4*)(Wsh + n * WPAD + k) = w;
    }

    float c[2][4][4];
#pragma unroll
    for (int mt = 0; mt < 2; mt++)
#pragma unroll
        for (int nt = 0; nt < 4; nt++)
#pragma unroll
            for (int i = 0; i < 4; i++) c[mt][nt][i] = 0.f;

#pragma unroll
    for (int kt = 0; kt < NT; kt++) {
        if (kt == 0)      asm volatile("cp.async.wait_group 3;" ::: "memory");
        else if (kt == 1) asm volatile("cp.async.wait_group 2;" ::: "memory");
        else if (kt == 2) asm volatile("cp.async.wait_group 1;" ::: "memory");
        else              asm volatile("cp.async.wait_group 0;" ::: "memory");
        __syncthreads();
        const float* As = Ash + kt * BM * APAD;
#pragma unroll
        for (int ks = 0; ks < 4; ks++) {
            const int k0 = ks * 8 + lt;
            unsigned ahi[2][4], alo[2][4];
#pragma unroll
            for (int mt = 0; mt < 2; mt++) {
                int ar = warp_m * 32 + mt * 16 + lg;
                float f0 = As[ar * APAD + k0];
                float f1 = As[(ar + 8) * APAD + k0];
                float f2 = As[ar * APAD + k0 + 4];
                float f3 = As[(ar + 8) * APAD + k0 + 4];
                split_tf32(f0, ahi[mt][0], alo[mt][0]);
                split_tf32(f1, ahi[mt][1], alo[mt][1]);
                split_tf32(f2, ahi[mt][2], alo[mt][2]);
                split_tf32(f3, ahi[mt][3], alo[mt][3]);
            }
            unsigned bhi[4][2], blo[4][2];
#pragma unroll
            for (int nt = 0; nt < 4; nt++) {
                int bn = warp_n * 32 + nt * 8 + lg;
                float g0 = Wsh[bn * WPAD + kt * BK + k0];
                float g1 = Wsh[bn * WPAD + kt * BK + k0 + 4];
                split_tf32(g0, bhi[nt][0], blo[nt][0]);
                split_tf32(g1, bhi[nt][1], blo[nt][1]);
            }
#pragma unroll
            for (int mt = 0; mt < 2; mt++)
#pragma unroll
                for (int nt = 0; nt < 4; nt++) {
                    mma_tf32(c[mt][nt], ahi[mt][0], ahi[mt][1], ahi[mt][2], ahi[mt][3],
                             bhi[nt][0], bhi[nt][1]);
                    mma_tf32(c[mt][nt], alo[mt][0], alo[mt][1], alo[mt][2], alo[mt][3],
                             bhi[nt][0], bhi[nt][1]);
                    mma_tf32(c[mt][nt], ahi[mt][0], ahi[mt][1], ahi[mt][2], ahi[mt][3],
                             blo[nt][0], blo[nt][1]);
                }
        }
    }

#pragma unroll
    for (int mt = 0; mt < 2; mt++) {
        long long r_lo = row0 + warp_m * 32 + mt * 16 + lg;
#pragma unroll
        for (int half = 0; half < 2; half++) {
            long long r = r_lo + half * 8;
            if (r >= MTOT) continue;
#pragma unroll
            for (int nt = 0; nt < 4; nt++) {
                int col = warp_n * 32 + nt * 8 + 2 * lt;
                *(__half2*)(hwh + r * 64 + col) =
                    __floats2half2_rn(c[mt][nt][half * 2 + 0], c[mt][nt][half * 2 + 1]);
            }
        }
    }
}

// ---------------- layer-2 GEMM (K=64, fp16 A with relu(A+b) on load, fp16 out) ----------------
__global__ void __launch_bounds__(256, 2)
gemm2_k(const __half* __restrict__ A, const float* __restrict__ Wsrc,
        const float* __restrict__ abias, __half* __restrict__ hwh) {
    constexpr int K = 64, BM = 128, BK = 32, NT = 2;
    constexpr int WPAD = K + 4;
    constexpr int APAD = BK + 4;

    extern __shared__ float sm[];
    float* Wsh = sm;
    float* Ash = sm + 64 * WPAD;

    const int tid = threadIdx.x;
    const int wid = tid >> 5, lane = tid & 31;
    const int warp_m = wid & 3, warp_n = wid >> 2;
    const int lg = lane >> 2, lt = lane & 3;
    const long long row0 = (long long)blockIdx.x * BM;

    for (int i = tid * 4; i < 64 * K; i += 256 * 4) {
        int n = i / K, k = i % K;
        float4 w = *(const float4*)(Wsrc + n * K + k);
        *(float4*)(Wsh + n * WPAD + k) = w;
    }

    float4 areg[4];
    auto lda = [&](int kt) {
#pragma unroll
        for (int it = 0; it < 4; it++) {
            int idx = it * 256 + tid;
            int r = idx >> 3, kq = idx & 7;
            long long grow = row0 + r;
            float4 v = make_float4(0.f, 0.f, 0.f, 0.f);
            if (grow < MTOT)
                v = load_h4_relu(A + grow * K + kt * BK + kq * 4, abias, kt * BK + kq * 4);
            areg[it] = v;
        }
    };
    auto sts = [&](int buf) {
        float* dst = Ash + buf * BM * APAD;
#pragma unroll
        for (int it = 0; it < 4; it++) {
            int idx = it * 256 + tid;
            int r = idx >> 3, kq = idx & 7;
            *(float4*)(dst + r * APAD + kq * 4) = areg[it];
        }
    };

    float c[2][4][4];
#pragma unroll
    for (int mt = 0; mt < 2; mt++)
#pragma unroll
        for (int nt = 0; nt < 4; nt++)
#pragma unroll
            for (int i = 0; i < 4; i++) c[mt][nt][i] = 0.f;

    lda(0);
    sts(0);

    for (int kt = 0; kt < NT; kt++) {
        __syncthreads();
        if (kt + 1 < NT) lda(kt + 1);
        const float* As = Ash + (kt & 1) * BM * APAD;
#pragma unroll
        for (int ks = 0; ks < 4; ks++) {
            const int k0 = ks * 8 + lt;
            unsigned ahi[2][4], alo[2][4];
#pragma unroll
            for (int mt = 0; mt < 2; mt++) {
                int ar = warp_m * 32 + mt * 16 + lg;
                float f0 = As[ar * APAD + k0];
                float f1 = As[(ar + 8) * APAD + k0];
                float f2 = As[ar * APAD + k0 + 4];
                float f3 = As[(ar + 8) * APAD + k0 + 4];
                split_tf32(f0, ahi[mt][0], alo[mt][0]);
                split_tf32(f1, ahi[mt][1], alo[mt][1]);
                split_tf32(f2, ahi[mt][2], alo[mt][2]);
                split_tf32(f3, ahi[mt][3], alo[mt][3]);
            }
            unsigned bhi[4][2], blo[4][2];
#pragma unroll
            for (int nt = 0; nt < 4; nt++) {
                int bn = warp_n * 32 + nt * 8 + lg;
                float g0 = Wsh[bn * WPAD + kt * BK + k0];
                float g1 = Wsh[bn * WPAD + kt * BK + k0 + 4];
                split_tf32(g0, bhi[nt][0], blo[nt][0]);
                split_tf32(g1, bhi[nt][1], blo[nt][1]);
            }
#pragma unroll
            for (int mt = 0; mt < 2; mt++)
#pragma unroll
                for (int nt = 0; nt < 4; nt++) {
                    mma_tf32(c[mt][nt], ahi[mt][0], ahi[mt][1], ahi[mt][2], ahi[mt][3],
                             bhi[nt][0], bhi[nt][1]);
                    mma_tf32(c[mt][nt], alo[mt][0], alo[mt][1], alo[mt][2], alo[mt][3],
                             bhi[nt][0], bhi[nt][1]);
                    mma_tf32(c[mt][nt], ahi[mt][0], ahi[mt][1], ahi[mt][2], ahi[mt][3],
                             blo[nt][0], blo[nt][1]);
                }
        }
        if (kt + 1 < NT) sts((kt + 1) & 1);
    }

#pragma unroll
    for (int mt = 0; mt < 2; mt++) {
        long long r_lo = row0 + warp_m * 32 + mt * 16 + lg;
#pragma unroll
        for (int half = 0; half < 2; half++) {
            long long r = r_lo + half * 8;
            if (r >= MTOT) continue;
#pragma unroll
            for (int nt = 0; nt < 4; nt++) {
                int col = warp_n * 32 + nt * 8 + 2 * lt;
                *(__half2*)(hwh + r * 64 + col) =
                    __floats2half2_rn(c[mt][nt][half * 2 + 0], c[mt][nt][half * 2 + 1]);
            }
        }
    }
}

// ---------------- merged K+V projection GEMM (fp16 A in, fp16 scatter out) ----------------
__global__ void __launch_bounds__(512, 1)
gemm_kv_k(const __half* __restrict__ A, const float* __restrict__ Wsrc,
          const float* __restrict__ abias, const float* __restrict__ ebias,
          const int* __restrict__ gidx, __half* __restrict__ gK, __half* __restrict__ gV) {
    constexpr int K = 64, BM = 128, BK = 32, NT = 2;
    constexpr int WPAD = K + 4;
    constexpr int APAD = BK + 4;

    extern __shared__ float sm[];
    float* Wsh = sm;
    float* Ash = sm + 128 * WPAD;

    const int tid = threadIdx.x;
    const int wid = tid >> 5, lane = tid & 31;
    const int warp_m = wid & 3, warp_n = wid >> 2;
    const int lg = lane >> 2, lt = lane & 3;
    const long long row0 = (long long)blockIdx.x * BM;

    for (int i = tid * 4; i < 128 * K; i += 512 * 4) {
        int n = i / K, k = i % K;
        float4 w = *(const float4*)(Wsrc + n * K + k);
        *(float4*)(Wsh + n * WPAD + k) = w;
    }

    float4 areg[2];
    auto lda = [&](int kt) {
#pragma unroll
        for (int it = 0; it < 2; it++) {
            int idx = it * 512 + tid;
            int r = idx >> 3, kq = idx & 7;
            long long grow = row0 + r;
            float4 v = make_float4(0.f, 0.f, 0.f, 0.f);
            if (grow < MTOT)
                v = load_h4_relu(A + grow * K + kt * BK + kq * 4, abias, kt * BK + kq * 4);
            areg[it] = v;
        }
    };
    auto sts = [&](int buf) {
        float* dst = Ash + buf * BM * APAD;
#pragma unroll
        for (int it = 0; it < 2; it++) {
            int idx = it * 512 + tid;
            int r = idx >> 3, kq = idx & 7;
            *(float4*)(dst + r * APAD + kq * 4) = areg[it];
        }
    };

    float c[2][4][4];
#pragma unroll
    for (int mt = 0; mt < 2; mt++)
#pragma unroll
        for (int nt = 0; nt < 4; nt++)
#pragma unroll
            for (int i = 0; i < 4; i++) c[mt][nt][i] = 0.f;

    lda(0);
    sts(0);

    for (int kt = 0; kt < NT; kt++) {
        __syncthreads();
        if (kt + 1 < NT) lda(kt + 1);
        const float* As = Ash + (kt & 1) * BM * APAD;
#pragma unroll
        for (int ks = 0; ks < 4; ks++) {
            const int k0 = ks * 8 + lt;
            unsigned ahi[2][4], alo[2][4];
#pragma unroll
            for (int mt = 0; mt < 2; mt++) {
                int ar = warp_m * 32 + mt * 16 + lg;
                float f0 = As[ar * APAD + k0];
                float f1 = As[(ar + 8) * APAD + k0];
                float f2 = As[ar * APAD + k0 + 4];
                float f3 = As[(ar + 8) * APAD + k0 + 4];
                split_tf32(f0, ahi[mt][0], alo[mt][0]);
                split_tf32(f1, ahi[mt][1], alo[mt][1]);
                split_tf32(f2, ahi[mt][2], alo[mt][2]);
                split_tf32(f3, ahi[mt][3], alo[mt][3]);
            }
            unsigned bhi[4][2], blo[4][2];
#pragma unroll
            for (int nt = 0; nt < 4; nt++) {
                int bn = warp_n * 32 + nt * 8 + lg;
                float g0 = Wsh[bn * WPAD + kt * BK + k0];
                float g1 = Wsh[bn * WPAD + kt * BK + k0 + 4];
                split_tf32(g0, bhi[nt][0], blo[nt][0]);
                split_tf32(g1, bhi[nt][1], blo[nt][1]);
            }
#pragma unroll
            for (int mt = 0; mt < 2; mt++)
#pragma unroll
                for (int nt = 0; nt < 4; nt++) {
                    mma_tf32(c[mt][nt], ahi[mt][0], ahi[mt][1], ahi[mt][2], ahi[mt][3],
                             bhi[nt][0], bhi[nt][1]);
                    mma_tf32(c[mt][nt], alo[mt][0], alo[mt][1], alo[mt][2], alo[mt][3],
                             bhi[nt][0], bhi[nt][1]);
                    mma_tf32(c[mt][nt], ahi[mt][0], ahi[mt][1], ahi[mt][2], ahi[mt][3],
                             blo[nt][0], blo[nt][1]);
                }
        }
        if (kt + 1 < NT) sts((kt + 1) & 1);
    }

#pragma unroll
    for (int mt = 0; mt < 2; mt++) {
        long long r_lo = row0 + warp_m * 32 + mt * 16 + lg;
#pragma unroll
        for (int half = 0; half < 2; half++) {
            long long r = r_lo + half * 8;
            if (r >= MTOT) continue;
            unsigned rr = (unsigned)r;
            unsigned t = rr / (unsigned)N_;
            unsigned n = rr - t * (unsigned)N_;
            int ridx = __ldg(gidx + (size_t)t * R_ + n);
            size_t rowoff = ((size_t)ridx * T_ + t) * 64;
#pragma unroll
            for (int nt = 0; nt < 4; nt++) {
                int col = warp_n * 32 + nt * 8 + 2 * lt;
                float2 b = *(const float2*)(ebias + col);
                __half* base = (col < 64 ? gK + rowoff + col : gV + rowoff + (col - 64));
                *(__half2*)base = __floats2half2_rn(c[mt][nt][half * 2 + 0] + b.x,
                                                    c[mt][nt][half * 2 + 1] + b.y);
            }
        }
    }
}

// ---------------- te9: relu(h2[t=9] + b2) scattered by gidx (standalone) ----------------
__global__ void te9_k(const __half* __restrict__ h2, const float* __restrict__ b2,
                      const int* __restrict__ gidx, float* __restrict__ te9) {
    int idx = blockIdx.x * blockDim.x + threadIdx.x;
    if (idx >= N_ * D_) return;
    int n = idx >> 6, c = idx & 63;
    float v = fmaxf(__half2float(h2[((size_t)9 * N_ + n) * 64 + c]) + b2[c], 0.f);
    te9[(size_t)__ldg(gidx + (size_t)9 * R_ + n) * 64 + c] = v;
}

// ---------------- tail ----------------
#define TAIL_WARPS 8
#define TAIL_SMEM  ((12288 + 704 + TAIL_WARPS * 1456) * 4)

__device__ __forceinline__ float warp_sum(float v) {
#pragma unroll
    for (int off = 16; off; off >>= 1) v += __shfl_xor_sync(0xffffffffu, v, off);
    return v;
}

__global__ void tail_k(const float* __restrict__ inW, const float* __restrict__ inB,
                       const float* __restrict__ outW, const float* __restrict__ outB,
                       const float* __restrict__ w1, const float* __restrict__ w2,
                       const float* __restrict__ w3, const float* __restrict__ w4,
                       const float* __restrict__ ln1g, const float* __restrict__ ln1b,
                       const float* __restrict__ ln2g, const float* __restrict__ ln2b,
                       const float* __restrict__ fcW, const float* __restrict__ fcB,
                       const float* __restrict__ te9, const __half* __restrict__ gK,
                       const __half* __restrict__ gV, float* __restrict__ out) {
    extern __shared__ float sh[];
    float* Wq = sh;
    float* Wo = sh + 4096;
    float* Wf = sh + 8192;
    float* cv = sh + 12288;

    int tid = threadIdx.x;
    for (int i = tid; i < 4096; i += TAIL_WARPS * 32) {
        int k = i >> 6, j = i & 63;
        Wq[i] = inW[j * 64 + k];
        Wo[i] = outW[j * 64 + k];
        Wf[i] = fcW[j * 64 + k];
    }
    if (tid < 64) {
        cv[tid]       = inB[tid];
        cv[64 + tid]  = outB[tid];
        cv[128 + tid] = fcB[tid];
        cv[192 + tid] = w1[(T_ - 1) * 64 + tid];
        cv[256 + tid] = w2[(T_ - 1) * 64 + tid];
        cv[320 + tid] = ln1g[tid];
        cv[384 + tid] = ln1b[tid];
        cv[448 + tid] = w3[tid];
        cv[512 + tid] = w4[tid];
        cv[576 + tid] = ln2g[tid];
        cv[640 + tid] = ln2b[tid];
    }
    __syncthreads();

    int warp = tid >> 5, lane = tid & 31;
    float* wb   = cv + 704 + warp * 1456;
    float* pvec = wb;
    float* pq   = wb + 64;
    float* kb   = wb + 128;
    float* vb   = wb + 768;
    float* sc   = wb + 1408;

    int gw = blockIdx.x * TAIL_WARPS + warp;
    int nw = gridDim.x * TAIL_WARPS;

    for (int r = gw; r < R_; r += nw) {
        pvec[lane]      = te9[(size_t)r * 64 + lane];
        pvec[lane + 32] = te9[(size_t)r * 64 + lane + 32];
        const __half2* kr = (const __half2*)(gK + (size_t)r * 640);
        const __half2* vr = (const __half2*)(gV + (size_t)r * 640);
        for (int i = lane; i < 320; i += 32) {
            *(float2*)(kb + 2 * i) = __half22float2(__ldg(kr + i));
            *(float2*)(vb + 2 * i) = __half22float2(__ldg(vr + i));
        }
        __syncwarp();

        float q0 = cv[lane], q1 = cv[lane + 32];
        for (int k = 0; k < 64; k++) {
            float xv = pvec[k];
            q0 = fmaf(xv, Wq[k * 64 + lane], q0);
            q1 = fmaf(xv, Wq[k * 64 + lane + 32], q1);
        }
        pq[lane] = q0; pq[lane + 32] = q1;
        __syncwarp();

        for (int p = lane; p < H_ * T_; p += 32) {
            int h = p / T_, tt = p - h * T_;
            const float* qh = pq + h * 16;
            const float* kh = kb + tt * 64 + h * 16;
            float s = 0.f;
#pragma unroll
            for (int d = 0; d < 16; d++) s = fmaf(qh[d], kh[d], s);
            sc[p] = s * 0.25f;
        }
        __syncwarp();

        if (lane < H_) {
            float mx = -1e30f;
#pragma unroll
            for (int tt = 0; tt < T_; tt++) mx = fmaxf(mx, sc[lane * T_ + tt]);
            float sm = 0.f;
#pragma unroll
            for (int tt = 0; tt < T_; tt++) {
                float ev = __expf(sc[lane * T_ + tt] - mx);
                sc[lane * T_ + tt] = ev; sm += ev;
            }
            float inv = 1.f / sm;
#pragma unroll
            for (int tt = 0; tt < T_; tt++) sc[lane * T_ + tt] *= inv;
        }
        __syncwarp();

        int h0 = lane >> 4, h1 = (lane + 32) >> 4;
        float a0 = 0.f, a1 = 0.f;
#pragma unroll
        for (int tt = 0; tt < T_; tt++) {
            a0 = fmaf(sc[h0 * T_ + tt], vb[tt * 64 + lane], a0);
            a1 = fmaf(sc[h1 * T_ + tt], vb[tt * 64 + lane + 32], a1);
        }
        pq[lane] = a0; pq[lane + 32] = a1;
        __syncwarp();

        float o0 = cv[64 + lane], o1 = cv[64 + lane + 32];
        for (int k = 0; k < 64; k++) {
            float xv = pq[k];
            o0 = fmaf(xv, Wo[k * 64 + lane], o0);
            o1 = fmaf(xv, Wo[k * 64 + lane + 32], o1);
        }

        float y0 = cv[192 + lane] * pvec[lane] + cv[256 + lane] * o0;
        float y1 = cv[192 + lane + 32] * pvec[lane + 32] + cv[256 + lane + 32] * o1;
        float mu = warp_sum(y0 + y1) * (1.f / 64.f);
        float d0 = y0 - mu, d1 = y1 - mu;
        float var = warp_sum(d0 * d0 + d1 * d1) * (1.f / 64.f);
        float rs = rsqrtf(var + 1e-5f);
        float f0 = d0 * rs * cv[320 + lane] + cv[384 + lane];
        float f1 = d1 * rs * cv[320 + lane + 32] + cv[384 + lane + 32];
        __syncwarp();
        pvec[lane] = f0; pvec[lane + 32] = f1;
        __syncwarp();

        float u0 = cv[128 + lane], u1 = cv[128 + lane + 32];
        for (int k = 0; k < 64; k++) {
            float xv = pvec[k];
            u0 = fmaf(xv, Wf[k * 64 + lane], u0);
            u1 = fmaf(xv, Wf[k * 64 + lane + 32], u1);
        }
        float z0 = cv[448 + lane] * f0 + cv[512 + lane] * u0;
        float z1 = cv[448 + lane + 32] * f1 + cv[512 + lane + 32] * u1;
        float mu2 = warp_sum(z0 + z1) * (1.f / 64.f);
        float e0 = z0 - mu2, e1 = z1 - mu2;
        float var2 = warp_sum(e0 * e0 + e1 * e1) * (1.f / 64.f);
        float rs2 = rsqrtf(var2 + 1e-5f);
        out[(size_t)r * 64 + lane]      = e0 * rs2 * cv[576 + lane] + cv[640 + lane];
        out[(size_t)r * 64 + lane + 32] = e1 * rs2 * cv[576 + lane + 32] + cv[640 + lane + 32];
        __syncwarp();
    }
}

// ---------------- launch ----------------
extern "C" void kernel_launch(void* const* d_in, const int* in_sizes, int n_in,
                              void* d_out, int out_size) {
    const float* x          = (const float*)d_in[0];
    const int*   edge_index = (const int*)  d_in[1];
    const float* edge_weight= (const float*)d_in[2];
    const int*   global_idx = (const int*)  d_in[3];
    const float* gcn1_w     = (const float*)d_in[4];
    const float* gcn1_b     = (const float*)d_in[5];
    const float* gcn2_w     = (const float*)d_in[6];
    const float* gcn2_b     = (const float*)d_in[7];
    const float* in_proj_w  = (const float*)d_in[8];
    const float* in_proj_b  = (const float*)d_in[9];
    const float* out_proj_w = (const float*)d_in[10];
    const float* out_proj_b = (const float*)d_in[11];
    const float* w1         = (const float*)d_in[12];
    const float* w2         = (const float*)d_in[13];
    const float* w3         = (const float*)d_in[14];
    const float* w4         = (const float*)d_in[15];
    const float* ln1_g      = (const float*)d_in[16];
    const float* ln1_b      = (const float*)d_in[17];
    const float* ln2_g      = (const float*)d_in[18];
    const float* ln2_b      = (const float*)d_in[19];
    const float* fc_w       = (const float*)d_in[20];
    const float* fc_b       = (const float*)d_in[21];
    float* out = (float*)d_out;

    float *deg, *te9;
    float2* degcnt;
    __half *hwh, *h1, *h2, *gk, *gv;
    int *offs, *offw, *bsum;
    unsigned* bucket;
    cudaGetSymbolAddress((void**)&degcnt, g_degcnt);
    cudaGetSymbolAddress((void**)&deg,  g_deg);
    cudaGetSymbolAddress((void**)&offs, g_offs);
    cudaGetSymbolAddress((void**)&offw, g_offw);
    cudaGetSymbolAddress((void**)&bsum, g_bsum);
    cudaGetSymbolAddress((void**)&bucket, g_bucket);
    cudaGetSymbolAddress((void**)&hwh, g_hwh);
    cudaGetSymbolAddress((void**)&h1,  g_h1);
    cudaGetSymbolAddress((void**)&h2,  g_h2);
    cudaGetSymbolAddress((void**)&gk,  g_k);
    cudaGetSymbolAddress((void**)&gv,  g_v);
    cudaGetSymbolAddress((void**)&te9, g_te9);

    const int SM_G1 = (64 * (128 + 4) + 4 * 128 * 36) * 4;   // 107520
    const int SM_G2 = (64 * (64 + 4)  + 2 * 128 * 36) * 4;   // 54272
    const int SM_KV = (128 * (64 + 4) + 2 * 128 * 36) * 4;   // 71680
    cudaFuncSetAttribute((const void*)gemm1_ca_k,
                         cudaFuncAttributeMaxDynamicSharedMemorySize, SM_G1);
    cudaFuncSetAttribute((const void*)gemm2_k,
                         cudaFuncAttributeMaxDynamicSharedMemorySize, SM_G2);
    cudaFuncSetAttribute((const void*)gemm_kv_k,
                         cudaFuncAttributeMaxDynamicSharedMemorySize, SM_KV);
    cudaFuncSetAttribute(tail_k, cudaFuncAttributeMaxDynamicSharedMemorySize, TAIL_SMEM);

    const int NB_M  = (MTOT + 255) / 256;
    const int NB_G  = (MTOT + 127) / 128;   // 3907
    const dim3 GB_E((E_ + 255) / 256, T_);
    const int NB_AG = (MTOT * 8 + 255) / 256;

    // high-priority side stream: its blocks win SM slots at gemm wave boundaries
    int prLo, prHi;
    cudaDeviceGetStreamPriorityRange(&prLo, &prHi);   // prHi = numerically-least = highest
    cudaStream_t s2;
    cudaStreamCreateWithPriority(&s2, cudaStreamNonBlocking, prHi);
    cudaEvent_t evFork, evJoin, evH2, evTe9;
    cudaEventCreateWithFlags(&evFork, cudaEventDisableTiming);
    cudaEventCreateWithFlags(&evJoin, cudaEventDisableTiming);
    cudaEventCreateWithFlags(&evH2,   cudaEventDisableTiming);
    cudaEventCreateWithFlags(&evTe9,  cudaEventDisableTiming);

    cudaEventRecord(evFork, 0);
    cudaStreamWaitEvent(s2, evFork, 0);

    // CSR build on high-priority side stream (overlaps with gemm1)
    init_k  <<<NB_M, 256, 0, s2>>>(degcnt);
    pass1_k <<<GB_E, 256, 0, s2>>>(degcnt, edge_index, edge_weight);
    scan1_k <<<NSCAN, 256, 0, s2>>>(degcnt, offs, bsum);
    scan2_k <<<1, 128, 0, s2>>>(bsum, NSCAN);
    scan3_k <<<NB_M, 256, 0, s2>>>(offs, offw, bsum, degcnt, deg);
    scatter_k<<<GB_E, 256, 0, s2>>>(edge_index, edge_weight, deg, offw, bucket);
    cudaEventRecord(evJoin, s2);

    // layer-1 GEMM on main stream, concurrent with CSR build
    gemm1_ca_k<<<NB_G, 256, SM_G1>>>(x, gcn1_w, hwh);

    cudaStreamWaitEvent(0, evJoin, 0);

    agg2_k<<<NB_AG, 256>>>(bucket, offs, offw, deg, hwh, h1);

    gemm2_k<<<NB_G, 256, SM_G2>>>(h1, gcn2_w, gcn1_b, hwh);
    agg2_k<<<NB_AG, 256>>>(bucket, offs, offw, deg, hwh, h2);
    cudaEventRecord(evH2, 0);

    // te9 (side, high priority) overlaps with gemm_kv (main) — both depend only on h2
    cudaStreamWaitEvent(s2, evH2, 0);
    te9_k<<<(N_ * D_ + 255) / 256, 256, 0, s2>>>(h2, gcn2_b, global_idx, te9);
    cudaEventRecord(evTe9, s2);

    gemm_kv_k<<<NB_G, 512, SM_KV>>>(h2, in_proj_w + 64 * 64, gcn2_b,
                                    in_proj_b + 64, global_idx, gk, gv);

    cudaStreamWaitEvent(0, evTe9, 0);
    tail_k<<<296, TAIL_WARPS * 32, TAIL_SMEM>>>(in_proj_w, in_proj_b, out_proj_w, out_proj_b,
                                                w1, w2, w3, w4, ln1_g, ln1_b, ln2_g, ln2_b,
                                                fc_w, fc_b, te9, gk, gv, out);
    // (stream/events intentionally not destroyed: destruction mid-capture is illegal;
    //  kernel_launch is invoked only a handful of times, host-side handles are tiny)
}